// round 8
// baseline (speedup 1.0000x reference)
#include <cuda_runtime.h>
#include <cuda_fp16.h>
#include <math.h>

#define B_ 2
#define T_ 32
#define H_ 64
#define W_ 64
#define C_ 32
#define WR_ 33
#define KS_ 15
#define BTC_ (B_*T_*C_)

__device__ __half2 d_R [B_*C_*WR_*T_*H_];  // (B,C,Wr,T,H) row-FFT output (h spatial)
__device__ __half2 d_Yr[B_*C_*WR_*T_*H_];  // (B,C,Wr,T,H) after col-inv FFT
__device__ float2  d_Kf[2*C_*WR_*H_];      // (2,C,Wr,slot) kernel spectra, slot-permuted
__device__ float   d_ctxp[2*BTC_];         // 2-part ctx partial sums

__device__ __forceinline__ float2 cmul(float2 a, float2 b){
  return make_float2(a.x*b.x - a.y*b.y, a.x*b.y + a.y*b.x);
}

// ---------------- register FFT8, DIF + output reorder to natural order ----------------
template<int INV>
__device__ __forceinline__ void fft8r(float2 v[8]){
  const float S = 0.70710678118654752f;
  {
    float2 u, w, d;
    u=v[0]; w=v[4]; v[0]=make_float2(u.x+w.x,u.y+w.y); v[4]=make_float2(u.x-w.x,u.y-w.y);
    u=v[1]; w=v[5]; v[1]=make_float2(u.x+w.x,u.y+w.y); d=make_float2(u.x-w.x,u.y-w.y);
    v[5]= INV? make_float2(S*(d.x-d.y), S*(d.x+d.y)) : make_float2(S*(d.x+d.y), S*(d.y-d.x));
    u=v[2]; w=v[6]; v[2]=make_float2(u.x+w.x,u.y+w.y); d=make_float2(u.x-w.x,u.y-w.y);
    v[6]= INV? make_float2(-d.y, d.x) : make_float2(d.y, -d.x);
    u=v[3]; w=v[7]; v[3]=make_float2(u.x+w.x,u.y+w.y); d=make_float2(u.x-w.x,u.y-w.y);
    v[7]= INV? make_float2(-S*(d.x+d.y), S*(d.x-d.y)) : make_float2(S*(d.y-d.x), -S*(d.x+d.y));
  }
  #pragma unroll
  for (int h=0; h<8; h+=4){
    float2 u, w, d;
    u=v[h];   w=v[h+2]; v[h]  =make_float2(u.x+w.x,u.y+w.y); v[h+2]=make_float2(u.x-w.x,u.y-w.y);
    u=v[h+1]; w=v[h+3]; v[h+1]=make_float2(u.x+w.x,u.y+w.y); d=make_float2(u.x-w.x,u.y-w.y);
    v[h+3]= INV? make_float2(-d.y, d.x) : make_float2(d.y, -d.x);
  }
  #pragma unroll
  for (int h=0; h<8; h+=2){
    float2 u=v[h], w=v[h+1];
    v[h]  =make_float2(u.x+w.x,u.y+w.y);
    v[h+1]=make_float2(u.x-w.x,u.y-w.y);
  }
  float2 t1=v[1]; v[1]=v[4]; v[4]=t1;
  float2 t3=v[3]; v[3]=v[6]; v[6]=t3;
}

// Forward: input (lane j=n2, reg n1): x[8*n1+j] -> output (lane k1, reg k2): X[k1+8*k2]
template<int INV>
__device__ __forceinline__ void fft64r(float2 v[8], const float2 tw[8], int lane8){
  fft8r<INV>(v);
  #pragma unroll
  for (int r=1;r<8;r++){
    float2 w = tw[r];
    if (INV) w.y = -w.y;
    v[r] = cmul(v[r], w);
  }
  #pragma unroll
  for (int m=4; m; m>>=1){
    #pragma unroll
    for (int i=0;i<8;i++){
      if (i & m) continue;
      bool up = (lane8 & m) != 0;
      float2 send = up ? v[i] : v[i+m];
      float2 got;
      got.x = __shfl_xor_sync(0xffffffffu, send.x, m);
      got.y = __shfl_xor_sync(0xffffffffu, send.y, m);
      if (up) v[i] = got; else v[i+m] = got;
    }
  }
  fft8r<INV>(v);
}

__device__ __forceinline__ void make_tw(float2 tw[8], int j){
  tw[0] = make_float2(1.f, 0.f);
  #pragma unroll
  for (int r=1;r<8;r++){
    float s, c;
    __sincosf(-0.098174770424681f * (float)(j*r), &s, &c);
    tw[r] = make_float2(c, s);
  }
}

// Hermitian partner fetch: rc[r] = Z[(64 - (j+8r)) mod 64], within 8-lane groups.
__device__ __forceinline__ void herm_partner(const float2 v[8], float2 rc[8], int j){
  int src = (8 - j) & 7;
  #pragma unroll
  for (int r=0;r<8;r++){
    float2 send = v[7-r];
    float2 got;
    got.x = __shfl_sync(0xffffffffu, send.x, src, 8);
    got.y = __shfl_sync(0xffffffffu, send.y, src, 8);
    rc[r] = got;
  }
  if (j == 0){
    rc[0]=v[0]; rc[1]=v[7]; rc[2]=v[6]; rc[3]=v[5];
    rc[4]=v[4]; rc[5]=v[3]; rc[6]=v[2]; rc[7]=v[1];
  }
}

// ---------------- K1: row rfft of x; block=(hc-half, b, t, 8-channel group) ----------------
__global__ void k_fwd(const float* __restrict__ x){
  __shared__ float  sx[8*64*10];        // [hl8][w64][c8 pad10]
  __shared__ float2 stg[8*33*10];       // [c8][wr33][hl8 pad10]
  __shared__ float  wsum[8][4][2];
  int tid = threadIdx.x, bid = blockIdx.x;
  int hh = bid & 1, cg = (bid>>1) & 3, t = (bid>>3) & 31, b = bid >> 8;
  int c0 = cg*8;
  int j = tid & 7, g = tid >> 3;        // 32 groups of 8 lanes
  int p = g & 3, hl8 = g >> 2;          // channel pair 0..3, local h 0..7
  int c2 = tid & 3;                     // load-phase channel-pair index
  float2 tw[8]; make_tw(tw, j);
  const float* xb = x + (size_t)(b*T_ + t)*H_*W_*C_ + c0;
  float a0 = 0.f, a1 = 0.f;

  for (int hc = hh*4; hc < hh*4 + 4; hc++){
    #pragma unroll
    for (int k8 = 0; k8 < 8; k8++){
      int i = tid + k8*256;
      int w = (i >> 2) & 63, hl = i >> 8;
      float2 zv = *(const float2*)(xb + (size_t)((hc*8 + hl)*64 + w)*C_ + c2*2);
      sx[(hl*64 + w)*10 + c2*2    ] = zv.x;
      sx[(hl*64 + w)*10 + c2*2 + 1] = zv.y;
      a0 += zv.x; a1 += zv.y;
    }
    __syncthreads();
    {
      float2 v[8];
      #pragma unroll
      for (int n1=0;n1<8;n1++)
        v[n1] = *(const float2*)&sx[(hl8*64 + 8*n1 + j)*10 + 2*p];
      fft64r<0>(v, tw, j);
      float2 rc[8];
      herm_partner(v, rc, j);
      #pragma unroll
      for (int r=0;r<8;r++){
        int k = j + 8*r;
        if (k <= 32){
          float2 A  = make_float2(0.5f*(v[r].x + rc[r].x), 0.5f*(v[r].y - rc[r].y));
          float2 Bv = make_float2(0.5f*(v[r].y + rc[r].y), 0.5f*(rc[r].x - v[r].x));
          stg[((2*p    )*33 + k)*10 + hl8] = A;
          stg[((2*p + 1)*33 + k)*10 + hl8] = Bv;
        }
      }
    }
    __syncthreads();
    for (int i = tid; i < 8*33*8; i += 256){
      int hl = i & 7;
      int wr = (i >> 3) % 33;
      int c  = i / 264;
      float2 z = stg[(c*33 + wr)*10 + hl];
      d_R[((size_t)(b*C_ + c0 + c)*WR_ + wr)*2048 + (size_t)t*64 + hc*8 + hl]
        = __floats2half2_rn(z.x, z.y);
    }
    __syncthreads();
  }
  // ctx partial reduction: classes by c2 (lane&3)
  a0 += __shfl_xor_sync(0xffffffffu, a0, 4);
  a1 += __shfl_xor_sync(0xffffffffu, a1, 4);
  a0 += __shfl_xor_sync(0xffffffffu, a0, 8);
  a1 += __shfl_xor_sync(0xffffffffu, a1, 8);
  a0 += __shfl_xor_sync(0xffffffffu, a0, 16);
  a1 += __shfl_xor_sync(0xffffffffu, a1, 16);
  int lane = tid & 31, warp = tid >> 5;
  if (lane < 4){ wsum[warp][lane][0] = a0; wsum[warp][lane][1] = a1; }
  __syncthreads();
  if (tid < 8){
    float s = 0.f;
    #pragma unroll
    for (int w=0;w<8;w++) s += wsum[w][tid>>1][tid&1];
    d_ctxp[hh*BTC_ + (b*T_ + t)*C_ + c0 + tid] = s * (1.0f/4096.0f);
  }
}

// ---------------- K3: padded rfft2 of conv kernels, slot-permuted column spectra ----------------
__global__ void k_kf(const float* __restrict__ ke, const float* __restrict__ ki){
  __shared__ float2 sb[WR_*64];       // [wr][h spatial]
  int tid = threadIdx.x;
  int e = blockIdx.x >> 5, c = blockIdx.x & 31;
  const float* kk = (e ? ki : ke) + c*KS_*KS_;
  int j = tid & 7, g = tid >> 3;
  float2 tw[8]; make_tw(tw, j);

  {
    int h0 = g << 1;
    float2 v[8];
    #pragma unroll
    for (int n1=0;n1<8;n1++){
      int w = 8*n1 + j;
      float v0 = 0.f, v1 = 0.f;
      if (w >= 24 && w < 39){
        if (h0   >= 24 && h0   < 39) v0 = kk[(h0  -24)*KS_ + (w-24)];
        if (h0+1 >= 24 && h0+1 < 39) v1 = kk[(h0+1-24)*KS_ + (w-24)];
      }
      v[n1] = make_float2(v0, v1);
    }
    fft64r<0>(v, tw, j);
    float2 rc[8];
    herm_partner(v, rc, j);
    #pragma unroll
    for (int r=0;r<8;r++){
      int k = j + 8*r;
      if (k <= 32){
        float2 A  = make_float2(0.5f*(v[r].x + rc[r].x), 0.5f*(v[r].y - rc[r].y));
        float2 Bv = make_float2(0.5f*(v[r].y + rc[r].y), 0.5f*(rc[r].x - v[r].x));
        sb[k*64 + h0    ] = A;
        sb[k*64 + h0 + 1] = Bv;
      }
    }
  }
  __syncthreads();
  size_t kb = ((size_t)(e*C_ + c)*WR_)*64;
  {
    int wr = g;
    float2 v[8];
    #pragma unroll
    for (int n1=0;n1<8;n1++) v[n1] = sb[wr*64 + 8*n1 + j];
    fft64r<0>(v, tw, j);
    #pragma unroll
    for (int r=0;r<8;r++) d_Kf[kb + (size_t)wr*64 + r*8 + j] = v[r];
  }
  if (tid < 32){
    float2 v[8];
    #pragma unroll
    for (int n1=0;n1<8;n1++) v[n1] = sb[32*64 + 8*n1 + j];
    fft64r<0>(v, tw, j);
    if ((tid >> 3) == 0){
      #pragma unroll
      for (int r=0;r<8;r++) d_Kf[kb + (size_t)32*64 + r*8 + j] = v[r];
    }
  }
}

// ---------------- K4: 2 tiles/block + in-block gate computation ----------------
__global__ void k_mid(const float* __restrict__ wA, const float* __restrict__ bA,
                      const float* __restrict__ wD, const float* __restrict__ bD,
                      const float* __restrict__ wM, const float* __restrict__ bM,
                      const float* __restrict__ wG, const float* __restrict__ bG,
                      const float* __restrict__ decay){
  __shared__ float sur[2][32*72];
  __shared__ float sui[2][32*72];
  __shared__ float sg[2][128];
  int tid = threadIdx.x;
  int b0 = blockIdx.x * 2;
  int j = tid & 7, t = tid >> 3;
  float2 tw[8]; make_tw(tw, j);

  // gates prelude: tid -> (tt, q, t2); one dot-32 each
  {
    int tt = tid >> 7, q = (tid >> 5) & 3, t2 = tid & 31;
    int bc = (b0 + tt) / 33;
    int b  = bc >> 5, c = bc & 31;
    const float* wv = (q==0) ? wA : (q==1) ? wD : (q==2) ? wM : wG;
    const float* bv = (q==0) ? bA : (q==1) ? bD : (q==2) ? bM : bG;
    float z = bv[c];
    int cb = (b*T_ + t2)*C_;
    #pragma unroll
    for (int k=0;k<32;k++)
      z += (d_ctxp[cb + k] + d_ctxp[BTC_ + cb + k]) * wv[k*32 + c];
    float val;
    if (q < 2){
      float dec = fminf(fmaxf(decay[c], 0.1f), 0.99f);
      val = dec / (1.0f + expf(-z));
    } else {
      val = (z > 20.0f) ? z : log1pf(expf(z));
    }
    sg[tt][q*32 + t2] = val;
  }

  #pragma unroll
  for (int tt=0; tt<2; tt++){
    size_t rbase = (size_t)(b0 + tt) * 2048;
    float2 v[8];
    #pragma unroll
    for (int n1=0;n1<8;n1++) v[n1] = __half22float2(d_R[rbase + t*64 + 8*n1 + j]);
    fft64r<0>(v, tw, j);
    #pragma unroll
    for (int r=0;r<8;r++){
      sur[tt][t*72 + r*8 + j] = v[r].x;
      sui[tt][t*72 + r*8 + j] = v[r].y;
    }
  }
  __syncthreads();

  if (tid < 128){
    int tt = tid >> 6, slot = tid & 63;
    int bid = b0 + tt;
    int bc = bid / 33;
    int wr = bid - bc*33;
    int c  = bc & 31;
    float2 KE = d_Kf[((size_t)(      c)*WR_ + wr)*64 + slot];
    float2 KI = d_Kf[((size_t)(C_ +  c)*WR_ + wr)*64 + slot];
    float2 X = make_float2(0.f,0.f), Y = make_float2(0.f,0.f);
    float* pr = sur[tt]; float* pi = sui[tt];
    const float* g = sg[tt];
    #pragma unroll
    for (int t2=0; t2<32; t2++){
      float a  = g[t2], dd = g[32+t2], m = g[64+t2], gg = g[96+t2];
      float2 U = make_float2(pr[t2*72 + slot], pi[t2*72 + slot]);
      float2 KIY = cmul(KI, Y);
      float2 KEX = cmul(KE, X);
      float2 nX = make_float2(a*X.x - m*KIY.x + U.x, a*X.y - m*KIY.y + U.y);
      float2 nY = make_float2(gg*KEX.x + dd*Y.x + 1e-10f, gg*KEX.y + dd*Y.y);
      pr[t2*72 + slot] = nY.x;
      pi[t2*72 + slot] = nY.y;
      X = nX; Y = nY;
    }
  }
  __syncthreads();

  #pragma unroll
  for (int tt=0; tt<2; tt++){
    size_t rbase = (size_t)(b0 + tt) * 2048;
    float2 v[8];
    #pragma unroll
    for (int r=0;r<8;r++){
      v[r].x = sur[tt][t*72 + r*8 + j];
      v[r].y = sui[tt][t*72 + r*8 + j];
    }
    fft64r<1>(v, tw, j);
    #pragma unroll
    for (int n1=0;n1<8;n1++)
      d_Yr[rbase + t*64 + 8*n1 + j] = __floats2half2_rn(v[n1].x, v[n1].y);
  }
}

// ---------------- K5: inverse row rfft; block = (hc-half, b, t, 8-channel group) ----------------
__global__ void k_inv(float* __restrict__ out){
  __shared__ float syr[8*33*9];     // [lc][wr][h8 pad9]
  __shared__ float syi[8*33*9];
  __shared__ float so[8*64*9];      // [h8][w64][c8 pad9]
  int tid = threadIdx.x;
  int bid = blockIdx.x;
  int hh = bid & 1;
  int cg = (bid >> 1) & 3;
  int t  = (bid >> 3) & 31;
  int b  = bid >> 8;
  int j = tid & 7, g = tid >> 3;
  int lc_g = g & 7, pr = g >> 3;     // group channel, local h-pair (0..3)
  float2 tw[8]; make_tw(tw, j);
  const float sc = 1.0f/4096.0f;
  size_t obase = ((size_t)(b*T_ + t)*4096)*32 + cg*8;

  for (int hc = hh*4; hc < hh*4 + 4; hc++){
    for (int i = tid; i < 8*33*8; i += 256){
      int lc = i >> 8;
      int rem = i - lc*264;
      int wr = rem >> 3, hl = rem & 7;
      float2 z = __half22float2(
        d_Yr[((size_t)(b*C_ + cg*8 + lc)*WR_ + wr)*2048 + (size_t)t*64 + hc*8 + hl]);
      syr[(lc*33 + wr)*9 + hl] = z.x;
      syi[(lc*33 + wr)*9 + hl] = z.y;
    }
    __syncthreads();
    {
      float2 v[8];
      #pragma unroll
      for (int r=0;r<8;r++){
        int k = j + 8*r;
        int wrk = (k <= 32) ? k : 64 - k;
        float sgn = (k <= 32) ? 1.f : -1.f;
        int base = (lc_g*33 + wrk)*9;
        float y0r = syr[base + 2*pr];
        float y0i = sgn * syi[base + 2*pr];
        float y1r = syr[base + 2*pr + 1];
        float y1i = sgn * syi[base + 2*pr + 1];
        v[r] = make_float2(y0r - y1i, y0i + y1r);
      }
      fft64r<1>(v, tw, j);
      #pragma unroll
      for (int n1=0;n1<8;n1++){
        int w = 8*n1 + j;
        so[((2*pr    )*64 + w)*9 + lc_g] = v[n1].x * sc;
        so[((2*pr + 1)*64 + w)*9 + lc_g] = v[n1].y * sc;
      }
    }
    __syncthreads();
    for (int i = tid; i < 8*64*8; i += 256){
      int lc = i & 7;
      int w  = (i >> 3) & 63;
      int hl = i >> 9;
      out[obase + (size_t)((hc*8 + hl)*64 + w)*32 + lc] = so[(hl*64 + w)*9 + lc];
    }
    __syncthreads();
  }
}

extern "C" void kernel_launch(void* const* d_in, const int* in_sizes, int n_in,
                              void* d_out, int out_size){
  const float* x  = (const float*)d_in[0];
  const float* wA = (const float*)d_in[1];
  const float* bA = (const float*)d_in[2];
  const float* wD = (const float*)d_in[3];
  const float* bD = (const float*)d_in[4];
  const float* wM = (const float*)d_in[5];
  const float* bM = (const float*)d_in[6];
  const float* wG = (const float*)d_in[7];
  const float* bG = (const float*)d_in[8];
  const float* dc = (const float*)d_in[9];
  const float* ke = (const float*)d_in[10];
  const float* ki = (const float*)d_in[11];
  float* out = (float*)d_out;

  k_kf   <<<2*C_,        256>>>(ke, ki);
  k_fwd  <<<B_*T_*4*2,   256>>>(x);                            // 512 blocks
  k_mid  <<<B_*C_*WR_/2, 256>>>(wA,bA,wD,bD,wM,bM,wG,bG,dc);   // 1056 blocks
  k_inv  <<<B_*T_*4*2,   256>>>(out);                          // 512 blocks
}

// round 12
// speedup vs baseline: 2.6306x; 2.6306x over previous
#include <cuda_runtime.h>
#include <cuda_fp16.h>
#include <math.h>

#define B_ 2
#define T_ 32
#define H_ 64
#define W_ 64
#define C_ 32
#define WR_ 33
#define KS_ 15
#define BTC_ (B_*T_*C_)

__device__ __half2 d_R [B_*C_*WR_*T_*H_];  // (B,C,Wr,T,H) row-FFT output (h spatial)
__device__ __half2 d_Yr[B_*C_*WR_*T_*H_];  // (B,C,Wr,T,H) after col-inv FFT
__device__ float2  d_Kf[2*C_*WR_*H_];      // (2,C,Wr,slot) kernel spectra, slot-permuted
__device__ float   d_ctxp[2*BTC_];         // 2-part ctx partial sums
__device__ float   d_gates[B_*C_*4*T_];    // (B,C,[a,d,m,g],T)

__device__ __forceinline__ float2 cmul(float2 a, float2 b){
  return make_float2(a.x*b.x - a.y*b.y, a.x*b.y + a.y*b.x);
}

// ---------------- register FFT8, DIF + output reorder to natural order ----------------
template<int INV>
__device__ __forceinline__ void fft8r(float2 v[8]){
  const float S = 0.70710678118654752f;
  {
    float2 u, w, d;
    u=v[0]; w=v[4]; v[0]=make_float2(u.x+w.x,u.y+w.y); v[4]=make_float2(u.x-w.x,u.y-w.y);
    u=v[1]; w=v[5]; v[1]=make_float2(u.x+w.x,u.y+w.y); d=make_float2(u.x-w.x,u.y-w.y);
    v[5]= INV? make_float2(S*(d.x-d.y), S*(d.x+d.y)) : make_float2(S*(d.x+d.y), S*(d.y-d.x));
    u=v[2]; w=v[6]; v[2]=make_float2(u.x+w.x,u.y+w.y); d=make_float2(u.x-w.x,u.y-w.y);
    v[6]= INV? make_float2(-d.y, d.x) : make_float2(d.y, -d.x);
    u=v[3]; w=v[7]; v[3]=make_float2(u.x+w.x,u.y+w.y); d=make_float2(u.x-w.x,u.y-w.y);
    v[7]= INV? make_float2(-S*(d.x+d.y), S*(d.x-d.y)) : make_float2(S*(d.y-d.x), -S*(d.x+d.y));
  }
  #pragma unroll
  for (int h=0; h<8; h+=4){
    float2 u, w, d;
    u=v[h];   w=v[h+2]; v[h]  =make_float2(u.x+w.x,u.y+w.y); v[h+2]=make_float2(u.x-w.x,u.y-w.y);
    u=v[h+1]; w=v[h+3]; v[h+1]=make_float2(u.x+w.x,u.y+w.y); d=make_float2(u.x-w.x,u.y-w.y);
    v[h+3]= INV? make_float2(-d.y, d.x) : make_float2(d.y, -d.x);
  }
  #pragma unroll
  for (int h=0; h<8; h+=2){
    float2 u=v[h], w=v[h+1];
    v[h]  =make_float2(u.x+w.x,u.y+w.y);
    v[h+1]=make_float2(u.x-w.x,u.y-w.y);
  }
  float2 t1=v[1]; v[1]=v[4]; v[4]=t1;
  float2 t3=v[3]; v[3]=v[6]; v[6]=t3;
}

// Forward: input (lane j=n2, reg n1): x[8*n1+j] -> output (lane k1, reg k2): X[k1+8*k2]
template<int INV>
__device__ __forceinline__ void fft64r(float2 v[8], const float2 tw[8], int lane8){
  fft8r<INV>(v);
  #pragma unroll
  for (int r=1;r<8;r++){
    float2 w = tw[r];
    if (INV) w.y = -w.y;
    v[r] = cmul(v[r], w);
  }
  #pragma unroll
  for (int m=4; m; m>>=1){
    #pragma unroll
    for (int i=0;i<8;i++){
      if (i & m) continue;
      bool up = (lane8 & m) != 0;
      float2 send = up ? v[i] : v[i+m];
      float2 got;
      got.x = __shfl_xor_sync(0xffffffffu, send.x, m);
      got.y = __shfl_xor_sync(0xffffffffu, send.y, m);
      if (up) v[i] = got; else v[i+m] = got;
    }
  }
  fft8r<INV>(v);
}

__device__ __forceinline__ void make_tw(float2 tw[8], int j){
  tw[0] = make_float2(1.f, 0.f);
  #pragma unroll
  for (int r=1;r<8;r++){
    float s, c;
    __sincosf(-0.098174770424681f * (float)(j*r), &s, &c);
    tw[r] = make_float2(c, s);
  }
}

// Hermitian partner fetch: rc[r] = Z[(64 - (j+8r)) mod 64], within 8-lane groups.
__device__ __forceinline__ void herm_partner(const float2 v[8], float2 rc[8], int j){
  int src = (8 - j) & 7;
  #pragma unroll
  for (int r=0;r<8;r++){
    float2 send = v[7-r];
    float2 got;
    got.x = __shfl_sync(0xffffffffu, send.x, src, 8);
    got.y = __shfl_sync(0xffffffffu, send.y, src, 8);
    rc[r] = got;
  }
  if (j == 0){
    rc[0]=v[0]; rc[1]=v[7]; rc[2]=v[6]; rc[3]=v[5];
    rc[4]=v[4]; rc[5]=v[3]; rc[6]=v[2]; rc[7]=v[1];
  }
}

// ---------------- K1: row rfft of x; block=(hc-half, b, t, 8-channel group) ----------------
__global__ void k_fwd(const float* __restrict__ x){
  __shared__ float  sx[8*64*10];        // [hl8][w64][c8 pad10]
  __shared__ float2 stg[8*33*10];       // [c8][wr33][hl8 pad10]
  __shared__ float  wsum[8][4][2];
  int tid = threadIdx.x, bid = blockIdx.x;
  int hh = bid & 1, cg = (bid>>1) & 3, t = (bid>>3) & 31, b = bid >> 8;
  int c0 = cg*8;
  int j = tid & 7, g = tid >> 3;        // 32 groups of 8 lanes
  int p = g & 3, hl8 = g >> 2;          // channel pair 0..3, local h 0..7
  int c2 = tid & 3;                     // load-phase channel-pair index
  float2 tw[8]; make_tw(tw, j);
  const float* xb = x + (size_t)(b*T_ + t)*H_*W_*C_ + c0;
  float a0 = 0.f, a1 = 0.f;

  for (int hc = hh*4; hc < hh*4 + 4; hc++){
    #pragma unroll
    for (int k8 = 0; k8 < 8; k8++){
      int i = tid + k8*256;
      int w = (i >> 2) & 63, hl = i >> 8;
      float2 zv = *(const float2*)(xb + (size_t)((hc*8 + hl)*64 + w)*C_ + c2*2);
      sx[(hl*64 + w)*10 + c2*2    ] = zv.x;
      sx[(hl*64 + w)*10 + c2*2 + 1] = zv.y;
      a0 += zv.x; a1 += zv.y;
    }
    __syncthreads();
    {
      float2 v[8];
      #pragma unroll
      for (int n1=0;n1<8;n1++)
        v[n1] = *(const float2*)&sx[(hl8*64 + 8*n1 + j)*10 + 2*p];
      fft64r<0>(v, tw, j);
      float2 rc[8];
      herm_partner(v, rc, j);
      #pragma unroll
      for (int r=0;r<8;r++){
        int k = j + 8*r;
        if (k <= 32){
          float2 A  = make_float2(0.5f*(v[r].x + rc[r].x), 0.5f*(v[r].y - rc[r].y));
          float2 Bv = make_float2(0.5f*(v[r].y + rc[r].y), 0.5f*(rc[r].x - v[r].x));
          stg[((2*p    )*33 + k)*10 + hl8] = A;
          stg[((2*p + 1)*33 + k)*10 + hl8] = Bv;
        }
      }
    }
    __syncthreads();
    for (int i = tid; i < 8*33*8; i += 256){
      int hl = i & 7;
      int wr = (i >> 3) % 33;
      int c  = i / 264;
      float2 z = stg[(c*33 + wr)*10 + hl];
      d_R[((size_t)(b*C_ + c0 + c)*WR_ + wr)*2048 + (size_t)t*64 + hc*8 + hl]
        = __floats2half2_rn(z.x, z.y);
    }
    __syncthreads();
  }
  // ctx partial reduction: classes by c2 (lane&3)
  a0 += __shfl_xor_sync(0xffffffffu, a0, 4);
  a1 += __shfl_xor_sync(0xffffffffu, a1, 4);
  a0 += __shfl_xor_sync(0xffffffffu, a0, 8);
  a1 += __shfl_xor_sync(0xffffffffu, a1, 8);
  a0 += __shfl_xor_sync(0xffffffffu, a0, 16);
  a1 += __shfl_xor_sync(0xffffffffu, a1, 16);
  int lane = tid & 31, warp = tid >> 5;
  if (lane < 4){ wsum[warp][lane][0] = a0; wsum[warp][lane][1] = a1; }
  __syncthreads();
  if (tid < 8){
    float s = 0.f;
    #pragma unroll
    for (int w=0;w<8;w++) s += wsum[w][tid>>1][tid&1];
    d_ctxp[hh*BTC_ + (b*T_ + t)*C_ + c0 + tid] = s * (1.0f/4096.0f);
  }
}

// ---------------- K2: gates (tiny GEMMs, coalesced ctx) ----------------
__global__ void k_gates(const float* __restrict__ wA, const float* __restrict__ bA,
                        const float* __restrict__ wD, const float* __restrict__ bD,
                        const float* __restrict__ wM, const float* __restrict__ bM,
                        const float* __restrict__ wG, const float* __restrict__ bG,
                        const float* __restrict__ decay){
  __shared__ float sctx[32];
  int bt = blockIdx.x;
  int c = threadIdx.x;
  sctx[c] = d_ctxp[bt*32 + c] + d_ctxp[BTC_ + bt*32 + c];
  __syncwarp();
  float za = bA[c], zd = bD[c], zm = bM[c], zg = bG[c];
  #pragma unroll
  for (int k = 0; k < 32; k++){
    float v = sctx[k];
    za += v * wA[k*32 + c];
    zd += v * wD[k*32 + c];
    zm += v * wM[k*32 + c];
    zg += v * wG[k*32 + c];
  }
  float dec = fminf(fmaxf(decay[c], 0.1f), 0.99f);
  float ga = dec / (1.0f + expf(-za));
  float gd = dec / (1.0f + expf(-zd));
  float gm = (zm > 20.0f) ? zm : log1pf(expf(zm));
  float gg = (zg > 20.0f) ? zg : log1pf(expf(zg));
  int b = bt >> 5, t = bt & 31;
  int base = (b*32 + c)*128 + t;
  d_gates[base +  0] = ga;
  d_gates[base + 32] = gd;
  d_gates[base + 64] = gm;
  d_gates[base + 96] = gg;
}

// ---------------- K3: padded rfft2 of conv kernels, slot-permuted column spectra ----------------
__global__ void k_kf(const float* __restrict__ ke, const float* __restrict__ ki){
  __shared__ float2 sb[WR_*64];       // [wr][h spatial]
  int tid = threadIdx.x;
  int e = blockIdx.x >> 5, c = blockIdx.x & 31;
  const float* kk = (e ? ki : ke) + c*KS_*KS_;
  int j = tid & 7, g = tid >> 3;
  float2 tw[8]; make_tw(tw, j);

  {
    int h0 = g << 1;
    float2 v[8];
    #pragma unroll
    for (int n1=0;n1<8;n1++){
      int w = 8*n1 + j;
      float v0 = 0.f, v1 = 0.f;
      if (w >= 24 && w < 39){
        if (h0   >= 24 && h0   < 39) v0 = kk[(h0  -24)*KS_ + (w-24)];
        if (h0+1 >= 24 && h0+1 < 39) v1 = kk[(h0+1-24)*KS_ + (w-24)];
      }
      v[n1] = make_float2(v0, v1);
    }
    fft64r<0>(v, tw, j);
    float2 rc[8];
    herm_partner(v, rc, j);
    #pragma unroll
    for (int r=0;r<8;r++){
      int k = j + 8*r;
      if (k <= 32){
        float2 A  = make_float2(0.5f*(v[r].x + rc[r].x), 0.5f*(v[r].y - rc[r].y));
        float2 Bv = make_float2(0.5f*(v[r].y + rc[r].y), 0.5f*(rc[r].x - v[r].x));
        sb[k*64 + h0    ] = A;
        sb[k*64 + h0 + 1] = Bv;
      }
    }
  }
  __syncthreads();
  size_t kb = ((size_t)(e*C_ + c)*WR_)*64;
  {
    int wr = g;
    float2 v[8];
    #pragma unroll
    for (int n1=0;n1<8;n1++) v[n1] = sb[wr*64 + 8*n1 + j];
    fft64r<0>(v, tw, j);
    #pragma unroll
    for (int r=0;r<8;r++) d_Kf[kb + (size_t)wr*64 + r*8 + j] = v[r];
  }
  if (tid < 32){
    float2 v[8];
    #pragma unroll
    for (int n1=0;n1<8;n1++) v[n1] = sb[32*64 + 8*n1 + j];
    fft64r<0>(v, tw, j);
    if ((tid >> 3) == 0){
      #pragma unroll
      for (int r=0;r<8;r++) d_Kf[kb + (size_t)32*64 + r*8 + j] = v[r];
    }
  }
}

// ---------------- K4: 2 tiles/block: col reg-FFT + recurrence + inverse col reg-FFT ----------------
__global__ void k_mid(){
  __shared__ float sur[2][32*72];
  __shared__ float sui[2][32*72];
  __shared__ float sg[2][128];
  int tid = threadIdx.x;
  int b0 = blockIdx.x * 2;
  int j = tid & 7, t = tid >> 3;
  float2 tw[8]; make_tw(tw, j);

  if (tid < 128) sg[0][tid]       = d_gates[(b0/33)*128 + tid];
  else           sg[1][tid - 128] = d_gates[((b0+1)/33)*128 + (tid - 128)];

  #pragma unroll
  for (int tt=0; tt<2; tt++){
    size_t rbase = (size_t)(b0 + tt) * 2048;
    float2 v[8];
    #pragma unroll
    for (int n1=0;n1<8;n1++) v[n1] = __half22float2(d_R[rbase + t*64 + 8*n1 + j]);
    fft64r<0>(v, tw, j);
    #pragma unroll
    for (int r=0;r<8;r++){
      sur[tt][t*72 + r*8 + j] = v[r].x;
      sui[tt][t*72 + r*8 + j] = v[r].y;
    }
  }
  __syncthreads();

  if (tid < 128){
    int tt = tid >> 6, slot = tid & 63;
    int bid = b0 + tt;
    int bc = bid / 33;
    int wr = bid - bc*33;
    int c  = bc & 31;
    float2 KE = d_Kf[((size_t)(      c)*WR_ + wr)*64 + slot];
    float2 KI = d_Kf[((size_t)(C_ +  c)*WR_ + wr)*64 + slot];
    float2 X = make_float2(0.f,0.f), Y = make_float2(0.f,0.f);
    float* pr = sur[tt]; float* pi = sui[tt];
    const float* g = sg[tt];
    #pragma unroll
    for (int t2=0; t2<32; t2++){
      float a  = g[t2], dd = g[32+t2], m = g[64+t2], gg = g[96+t2];
      float2 U = make_float2(pr[t2*72 + slot], pi[t2*72 + slot]);
      float2 KIY = cmul(KI, Y);
      float2 KEX = cmul(KE, X);
      float2 nX = make_float2(a*X.x - m*KIY.x + U.x, a*X.y - m*KIY.y + U.y);
      float2 nY = make_float2(gg*KEX.x + dd*Y.x + 1e-10f, gg*KEX.y + dd*Y.y);
      pr[t2*72 + slot] = nY.x;
      pi[t2*72 + slot] = nY.y;
      X = nX; Y = nY;
    }
  }
  __syncthreads();

  #pragma unroll
  for (int tt=0; tt<2; tt++){
    size_t rbase = (size_t)(b0 + tt) * 2048;
    float2 v[8];
    #pragma unroll
    for (int r=0;r<8;r++){
      v[r].x = sur[tt][t*72 + r*8 + j];
      v[r].y = sui[tt][t*72 + r*8 + j];
    }
    fft64r<1>(v, tw, j);
    #pragma unroll
    for (int n1=0;n1<8;n1++)
      d_Yr[rbase + t*64 + 8*n1 + j] = __floats2half2_rn(v[n1].x, v[n1].y);
  }
}

// ---------------- K5: inverse row rfft, 64-bit vectorized; block=(hc-half,b,t,cg8) ----------------
__global__ void k_inv(float* __restrict__ out){
  __shared__ float2 sy[8*33*9];     // [(lc*33+wr)*9 + hl]  (re,im), hl 0..7 + pad
  __shared__ float  so[8*64*10];    // [h8][w64][c8 pad10]
  int tid = threadIdx.x, bid = blockIdx.x;
  int hh = bid & 1;
  int cg = (bid >> 1) & 3;
  int t  = (bid >> 3) & 31;
  int b  = bid >> 8;
  int j = tid & 7, g = tid >> 3;
  int lc_g = g & 7, pr = g >> 3;     // group channel, local h-pair (0..3)
  float2 tw[8]; make_tw(tw, j);
  const float sc = 1.0f/4096.0f;
  size_t obase = ((size_t)(b*T_ + t)*4096)*32 + cg*8;
  const uint2* yb = (const uint2*)d_Yr + ((size_t)(b*C_ + cg*8)*WR_)*1024 + t*32;

  for (int hc = hh*4; hc < hh*4 + 4; hc++){
    // stage A: vector load (2 half2 per LDG), q = lc*33+wr = i>>2
    for (int i = tid; i < 1056; i += 256){
      int q = i >> 2, hp = i & 3;
      uint2 zz = yb[(size_t)q*1024 + hc*4 + hp];
      sy[q*9 + 2*hp    ] = __half22float2(*(__half2*)&zz.x);
      sy[q*9 + 2*hp + 1] = __half22float2(*(__half2*)&zz.y);
    }
    __syncthreads();
    // stage B: Hermitian-extend + reg iFFT (float2 gathers)
    {
      float2 v[8];
      #pragma unroll
      for (int r=0;r<8;r++){
        int k = j + 8*r;
        int wrk = (k <= 32) ? k : 64 - k;
        float sgn = (k <= 32) ? 1.f : -1.f;
        int base = (lc_g*33 + wrk)*9;
        float2 y0 = sy[base + 2*pr];
        float2 y1 = sy[base + 2*pr + 1];
        v[r] = make_float2(y0.x - sgn*y1.y, sgn*y0.y + y1.x);
      }
      fft64r<1>(v, tw, j);
      #pragma unroll
      for (int n1=0;n1<8;n1++){
        int w = 8*n1 + j;
        so[((2*pr    )*64 + w)*10 + lc_g] = v[n1].x * sc;
        so[((2*pr + 1)*64 + w)*10 + lc_g] = v[n1].y * sc;
      }
    }
    __syncthreads();
    // stage C: float2 loads + 64-bit coalesced stores
    #pragma unroll
    for (int ii = 0; ii < 8; ii++){
      int i = tid + ii*256;
      int c2 = i & 3, w = (i >> 2) & 63, hl = i >> 8;
      float2 val = *(const float2*)&so[(hl*64 + w)*10 + c2*2];
      *(float2*)&out[obase + (size_t)((hc*8 + hl)*64 + w)*32 + c2*2] = val;
    }
    __syncthreads();
  }
}

extern "C" void kernel_launch(void* const* d_in, const int* in_sizes, int n_in,
                              void* d_out, int out_size){
  const float* x  = (const float*)d_in[0];
  const float* wA = (const float*)d_in[1];
  const float* bA = (const float*)d_in[2];
  const float* wD = (const float*)d_in[3];
  const float* bD = (const float*)d_in[4];
  const float* wM = (const float*)d_in[5];
  const float* bM = (const float*)d_in[6];
  const float* wG = (const float*)d_in[7];
  const float* bG = (const float*)d_in[8];
  const float* dc = (const float*)d_in[9];
  const float* ke = (const float*)d_in[10];
  const float* ki = (const float*)d_in[11];
  float* out = (float*)d_out;

  k_kf   <<<2*C_,        256>>>(ke, ki);
  k_fwd  <<<B_*T_*4*2,   256>>>(x);                            // 512 blocks
  k_gates<<<B_*T_,       32>>>(wA,bA,wD,bD,wM,bM,wG,bG,dc);
  k_mid  <<<B_*C_*WR_/2, 256>>>();                             // 1056 blocks
  k_inv  <<<B_*T_*4*2,   256>>>(out);                          // 512 blocks
}

// round 14
// speedup vs baseline: 2.6993x; 1.0261x over previous
#include <cuda_runtime.h>
#include <cuda_fp16.h>
#include <math.h>

#define B_ 2
#define T_ 32
#define H_ 64
#define W_ 64
#define C_ 32
#define WR_ 33
#define KS_ 15
#define BTC_ (B_*T_*C_)

__device__ __half2 d_R [B_*C_*WR_*T_*H_];  // (B,C,Wr,T,H) row-FFT output (h spatial)
__device__ __half2 d_Yr[B_*C_*WR_*T_*H_];  // (B,C,Wr,T,H) after col-inv FFT
__device__ float2  d_Kf[2*C_*WR_*H_];      // (2,C,Wr,slot) kernel spectra, slot-permuted
__device__ float   d_ctxp[2*BTC_];         // 2-part ctx partial sums
__device__ float   d_gates[B_*C_*4*T_];    // (B,C,[a,d,m,g],T)

__device__ __forceinline__ float2 cmul(float2 a, float2 b){
  return make_float2(a.x*b.x - a.y*b.y, a.x*b.y + a.y*b.x);
}

// ---------------- register FFT8, DIF + output reorder to natural order ----------------
template<int INV>
__device__ __forceinline__ void fft8r(float2 v[8]){
  const float S = 0.70710678118654752f;
  {
    float2 u, w, d;
    u=v[0]; w=v[4]; v[0]=make_float2(u.x+w.x,u.y+w.y); v[4]=make_float2(u.x-w.x,u.y-w.y);
    u=v[1]; w=v[5]; v[1]=make_float2(u.x+w.x,u.y+w.y); d=make_float2(u.x-w.x,u.y-w.y);
    v[5]= INV? make_float2(S*(d.x-d.y), S*(d.x+d.y)) : make_float2(S*(d.x+d.y), S*(d.y-d.x));
    u=v[2]; w=v[6]; v[2]=make_float2(u.x+w.x,u.y+w.y); d=make_float2(u.x-w.x,u.y-w.y);
    v[6]= INV? make_float2(-d.y, d.x) : make_float2(d.y, -d.x);
    u=v[3]; w=v[7]; v[3]=make_float2(u.x+w.x,u.y+w.y); d=make_float2(u.x-w.x,u.y-w.y);
    v[7]= INV? make_float2(-S*(d.x+d.y), S*(d.x-d.y)) : make_float2(S*(d.y-d.x), -S*(d.x+d.y));
  }
  #pragma unroll
  for (int h=0; h<8; h+=4){
    float2 u, w, d;
    u=v[h];   w=v[h+2]; v[h]  =make_float2(u.x+w.x,u.y+w.y); v[h+2]=make_float2(u.x-w.x,u.y-w.y);
    u=v[h+1]; w=v[h+3]; v[h+1]=make_float2(u.x+w.x,u.y+w.y); d=make_float2(u.x-w.x,u.y-w.y);
    v[h+3]= INV? make_float2(-d.y, d.x) : make_float2(d.y, -d.x);
  }
  #pragma unroll
  for (int h=0; h<8; h+=2){
    float2 u=v[h], w=v[h+1];
    v[h]  =make_float2(u.x+w.x,u.y+w.y);
    v[h+1]=make_float2(u.x-w.x,u.y-w.y);
  }
  float2 t1=v[1]; v[1]=v[4]; v[4]=t1;
  float2 t3=v[3]; v[3]=v[6]; v[6]=t3;
}

// Forward: input (lane j=n2, reg n1): x[8*n1+j] -> output (lane k1, reg k2): X[k1+8*k2]
template<int INV>
__device__ __forceinline__ void fft64r(float2 v[8], const float2 tw[8], int lane8){
  fft8r<INV>(v);
  #pragma unroll
  for (int r=1;r<8;r++){
    float2 w = tw[r];
    if (INV) w.y = -w.y;
    v[r] = cmul(v[r], w);
  }
  #pragma unroll
  for (int m=4; m; m>>=1){
    #pragma unroll
    for (int i=0;i<8;i++){
      if (i & m) continue;
      bool up = (lane8 & m) != 0;
      float2 send = up ? v[i] : v[i+m];
      float2 got;
      got.x = __shfl_xor_sync(0xffffffffu, send.x, m);
      got.y = __shfl_xor_sync(0xffffffffu, send.y, m);
      if (up) v[i] = got; else v[i+m] = got;
    }
  }
  fft8r<INV>(v);
}

__device__ __forceinline__ void make_tw(float2 tw[8], int j){
  tw[0] = make_float2(1.f, 0.f);
  #pragma unroll
  for (int r=1;r<8;r++){
    float s, c;
    __sincosf(-0.098174770424681f * (float)(j*r), &s, &c);
    tw[r] = make_float2(c, s);
  }
}

// Hermitian partner fetch: rc[r] = Z[(64 - (j+8r)) mod 64], within 8-lane groups.
__device__ __forceinline__ void herm_partner(const float2 v[8], float2 rc[8], int j){
  int src = (8 - j) & 7;
  #pragma unroll
  for (int r=0;r<8;r++){
    float2 send = v[7-r];
    float2 got;
    got.x = __shfl_sync(0xffffffffu, send.x, src, 8);
    got.y = __shfl_sync(0xffffffffu, send.y, src, 8);
    rc[r] = got;
  }
  if (j == 0){
    rc[0]=v[0]; rc[1]=v[7]; rc[2]=v[6]; rc[3]=v[5];
    rc[4]=v[4]; rc[5]=v[3]; rc[6]=v[2]; rc[7]=v[1];
  }
}

// ---------------- K1: row rfft of x; block=(hc-half, b, t, 8-channel group) ----------------
__global__ void k_fwd(const float* __restrict__ x){
  __shared__ float  sx[8*64*12];        // [hl8][w64][c8 pad12]  (16B-aligned c4 groups)
  __shared__ float2 stg[8*33*10];       // [c8][wr33][hl8 pad10]
  __shared__ float  wsum[8][2][4];
  int tid = threadIdx.x, bid = blockIdx.x;
  int hh = bid & 1, cg = (bid>>1) & 3, t = (bid>>3) & 31, b = bid >> 8;
  int c0 = cg*8;
  int j = tid & 7, g = tid >> 3;        // 32 groups of 8 lanes
  int p = g & 3, hl8 = g >> 2;          // channel pair 0..3, local h 0..7
  int c4 = tid & 1;                     // load-phase 4-channel group
  float2 tw[8]; make_tw(tw, j);
  const float* xb = x + (size_t)(b*T_ + t)*H_*W_*C_ + c0;
  float acc[4] = {0.f, 0.f, 0.f, 0.f};
  uint2* dR2 = (uint2*)d_R;

  for (int hc = hh*4; hc < hh*4 + 4; hc++){
    // float4 coalesced loads: i = hl*128 + w*2 + c4
    #pragma unroll
    for (int k4 = 0; k4 < 4; k4++){
      int i = tid + k4*256;
      int w = (i >> 1) & 63, hl = i >> 7;
      float4 zv = *(const float4*)(xb + (size_t)((hc*8 + hl)*64 + w)*C_ + c4*4);
      *(float4*)&sx[(hl*64 + w)*12 + c4*4] = zv;
      acc[0] += zv.x; acc[1] += zv.y; acc[2] += zv.z; acc[3] += zv.w;
    }
    __syncthreads();
    {
      float2 v[8];
      #pragma unroll
      for (int n1=0;n1<8;n1++)
        v[n1] = *(const float2*)&sx[(hl8*64 + 8*n1 + j)*12 + 2*p];
      fft64r<0>(v, tw, j);
      float2 rc[8];
      herm_partner(v, rc, j);
      #pragma unroll
      for (int r=0;r<8;r++){
        int k = j + 8*r;
        if (k <= 32){
          float2 A  = make_float2(0.5f*(v[r].x + rc[r].x), 0.5f*(v[r].y - rc[r].y));
          float2 Bv = make_float2(0.5f*(v[r].y + rc[r].y), 0.5f*(rc[r].x - v[r].x));
          stg[((2*p    )*33 + k)*10 + hl8] = A;
          stg[((2*p + 1)*33 + k)*10 + hl8] = Bv;
        }
      }
    }
    __syncthreads();
    // uint2 stores (2 h per STG.64)
    for (int i = tid; i < 8*33*4; i += 256){
      int hp = i & 3;
      int wr = (i >> 2) % 33;
      int c  = i / 132;
      float2 z0 = stg[(c*33 + wr)*10 + 2*hp];
      float2 z1 = stg[(c*33 + wr)*10 + 2*hp + 1];
      uint2 val;
      *(__half2*)&val.x = __floats2half2_rn(z0.x, z0.y);
      *(__half2*)&val.y = __floats2half2_rn(z1.x, z1.y);
      dR2[((size_t)(b*C_ + c0 + c)*WR_ + wr)*1024 + t*32 + hc*4 + hp] = val;
    }
    __syncthreads();
  }
  // ctx partial reduction: classes by c4 (tid&1)
  #pragma unroll
  for (int m=2; m<=16; m<<=1){
    #pragma unroll
    for (int q=0;q<4;q++) acc[q] += __shfl_xor_sync(0xffffffffu, acc[q], m);
  }
  int lane = tid & 31, warp = tid >> 5;
  if (lane < 2){
    #pragma unroll
    for (int q=0;q<4;q++) wsum[warp][lane][q] = acc[q];
  }
  __syncthreads();
  if (tid < 8){
    float s = 0.f;
    #pragma unroll
    for (int w=0;w<8;w++) s += wsum[w][tid>>2][tid&3];
    d_ctxp[hh*BTC_ + (b*T_ + t)*C_ + c0 + tid] = s * (1.0f/4096.0f);
  }
}

// ---------------- K2: gates (tiny GEMMs, coalesced ctx) ----------------
__global__ void k_gates(const float* __restrict__ wA, const float* __restrict__ bA,
                        const float* __restrict__ wD, const float* __restrict__ bD,
                        const float* __restrict__ wM, const float* __restrict__ bM,
                        const float* __restrict__ wG, const float* __restrict__ bG,
                        const float* __restrict__ decay){
  __shared__ float sctx[32];
  int bt = blockIdx.x;
  int c = threadIdx.x;
  sctx[c] = d_ctxp[bt*32 + c] + d_ctxp[BTC_ + bt*32 + c];
  __syncwarp();
  float za = bA[c], zd = bD[c], zm = bM[c], zg = bG[c];
  #pragma unroll
  for (int k = 0; k < 32; k++){
    float v = sctx[k];
    za += v * wA[k*32 + c];
    zd += v * wD[k*32 + c];
    zm += v * wM[k*32 + c];
    zg += v * wG[k*32 + c];
  }
  float dec = fminf(fmaxf(decay[c], 0.1f), 0.99f);
  float ga = dec / (1.0f + expf(-za));
  float gd = dec / (1.0f + expf(-zd));
  float gm = (zm > 20.0f) ? zm : log1pf(expf(zm));
  float gg = (zg > 20.0f) ? zg : log1pf(expf(zg));
  int b = bt >> 5, t = bt & 31;
  int base = (b*32 + c)*128 + t;
  d_gates[base +  0] = ga;
  d_gates[base + 32] = gd;
  d_gates[base + 64] = gm;
  d_gates[base + 96] = gg;
}

// ---------------- K3: padded rfft2 of conv kernels, slot-permuted column spectra ----------------
__global__ void k_kf(const float* __restrict__ ke, const float* __restrict__ ki){
  __shared__ float2 sb[WR_*64];       // [wr][h spatial]
  int tid = threadIdx.x;
  int e = blockIdx.x >> 5, c = blockIdx.x & 31;
  const float* kk = (e ? ki : ke) + c*KS_*KS_;
  int j = tid & 7, g = tid >> 3;
  float2 tw[8]; make_tw(tw, j);

  {
    int h0 = g << 1;
    float2 v[8];
    #pragma unroll
    for (int n1=0;n1<8;n1++){
      int w = 8*n1 + j;
      float v0 = 0.f, v1 = 0.f;
      if (w >= 24 && w < 39){
        if (h0   >= 24 && h0   < 39) v0 = kk[(h0  -24)*KS_ + (w-24)];
        if (h0+1 >= 24 && h0+1 < 39) v1 = kk[(h0+1-24)*KS_ + (w-24)];
      }
      v[n1] = make_float2(v0, v1);
    }
    fft64r<0>(v, tw, j);
    float2 rc[8];
    herm_partner(v, rc, j);
    #pragma unroll
    for (int r=0;r<8;r++){
      int k = j + 8*r;
      if (k <= 32){
        float2 A  = make_float2(0.5f*(v[r].x + rc[r].x), 0.5f*(v[r].y - rc[r].y));
        float2 Bv = make_float2(0.5f*(v[r].y + rc[r].y), 0.5f*(rc[r].x - v[r].x));
        sb[k*64 + h0    ] = A;
        sb[k*64 + h0 + 1] = Bv;
      }
    }
  }
  __syncthreads();
  size_t kb = ((size_t)(e*C_ + c)*WR_)*64;
  {
    int wr = g;
    float2 v[8];
    #pragma unroll
    for (int n1=0;n1<8;n1++) v[n1] = sb[wr*64 + 8*n1 + j];
    fft64r<0>(v, tw, j);
    #pragma unroll
    for (int r=0;r<8;r++) d_Kf[kb + (size_t)wr*64 + r*8 + j] = v[r];
  }
  if (tid < 32){
    float2 v[8];
    #pragma unroll
    for (int n1=0;n1<8;n1++) v[n1] = sb[32*64 + 8*n1 + j];
    fft64r<0>(v, tw, j);
    if ((tid >> 3) == 0){
      #pragma unroll
      for (int r=0;r<8;r++) d_Kf[kb + (size_t)32*64 + r*8 + j] = v[r];
    }
  }
}

// ---------------- K4: 2 tiles/block, float2 smem (pitch 72): FFT + recurrence + iFFT ----------------
__global__ void k_mid(){
  __shared__ float2 syc[2][32*72];   // [t][slot] pitch 72 float2 (576B row: conflict-free)
  __shared__ float  sg[2][128];
  int tid = threadIdx.x;
  int b0 = blockIdx.x * 2;
  int j = tid & 7, t = tid >> 3;
  float2 tw[8]; make_tw(tw, j);

  if (tid < 128) sg[0][tid]       = d_gates[(b0/33)*128 + tid];
  else           sg[1][tid - 128] = d_gates[((b0+1)/33)*128 + (tid - 128)];

  #pragma unroll
  for (int tt=0; tt<2; tt++){
    size_t rbase = (size_t)(b0 + tt) * 2048;
    float2 v[8];
    #pragma unroll
    for (int n1=0;n1<8;n1++) v[n1] = __half22float2(d_R[rbase + t*64 + 8*n1 + j]);
    fft64r<0>(v, tw, j);
    #pragma unroll
    for (int r=0;r<8;r++) syc[tt][t*72 + r*8 + j] = v[r];
  }
  __syncthreads();

  if (tid < 128){
    int tt = tid >> 6, slot = tid & 63;
    int bid = b0 + tt;
    int bc = bid / 33;
    int wr = bid - bc*33;
    int c  = bc & 31;
    float2 KE = d_Kf[((size_t)(      c)*WR_ + wr)*64 + slot];
    float2 KI = d_Kf[((size_t)(C_ +  c)*WR_ + wr)*64 + slot];
    float2 X = make_float2(0.f,0.f), Y = make_float2(0.f,0.f);
    float2* p2 = syc[tt];
    const float* g = sg[tt];
    #pragma unroll
    for (int t2=0; t2<32; t2++){
      float a  = g[t2], dd = g[32+t2], m = g[64+t2], gg = g[96+t2];
      float2 U = p2[t2*72 + slot];
      float2 KIY = cmul(KI, Y);
      float2 KEX = cmul(KE, X);
      float2 nX = make_float2(a*X.x - m*KIY.x + U.x, a*X.y - m*KIY.y + U.y);
      float2 nY = make_float2(gg*KEX.x + dd*Y.x + 1e-10f, gg*KEX.y + dd*Y.y);
      p2[t2*72 + slot] = nY;
      X = nX; Y = nY;
    }
  }
  __syncthreads();

  #pragma unroll
  for (int tt=0; tt<2; tt++){
    size_t rbase = (size_t)(b0 + tt) * 2048;
    float2 v[8];
    #pragma unroll
    for (int r=0;r<8;r++) v[r] = syc[tt][t*72 + r*8 + j];
    fft64r<1>(v, tw, j);
    #pragma unroll
    for (int n1=0;n1<8;n1++)
      d_Yr[rbase + t*64 + 8*n1 + j] = __floats2half2_rn(v[n1].x, v[n1].y);
  }
}

// ---------------- K5: inverse row rfft, 128-bit vectorized; block=(hc-half,b,t,cg8) ----------------
__global__ void k_inv(float* __restrict__ out){
  __shared__ float2 sy[8*33*9];     // [(lc*33+wr)*9 + hl]  (re,im), hl 0..7 + pad
  __shared__ float  so[8*64*12];    // [h8][w64][c8 pad12]  (16B-aligned c4 groups)
  int tid = threadIdx.x, bid = blockIdx.x;
  int hh = bid & 1;
  int cg = (bid >> 1) & 3;
  int t  = (bid >> 3) & 31;
  int b  = bid >> 8;
  int j = tid & 7, g = tid >> 3;
  int lc_g = g & 7, pr = g >> 3;     // group channel, local h-pair (0..3)
  float2 tw[8]; make_tw(tw, j);
  const float sc = 1.0f/4096.0f;
  size_t obase = ((size_t)(b*T_ + t)*4096)*32 + cg*8;
  const uint4* yb4 = (const uint4*)d_Yr + ((size_t)(b*C_ + cg*8)*WR_)*512 + t*16;

  for (int hc = hh*4; hc < hh*4 + 4; hc++){
    // stage A: uint4 loads (4 half2 per LDG.128), q = lc*33+wr = i>>1
    for (int i = tid; i < 528; i += 256){
      int q = i >> 1, hp2 = i & 1;
      uint4 zz = yb4[(size_t)q*512 + hc*2 + hp2];
      const __half2* hz = (const __half2*)&zz;
      #pragma unroll
      for (int m=0;m<4;m++) sy[q*9 + 4*hp2 + m] = __half22float2(hz[m]);
    }
    __syncthreads();
    // stage B: Hermitian-extend + reg iFFT (float2 gathers), scalar bank-exact so writes
    {
      float2 v[8];
      #pragma unroll
      for (int r=0;r<8;r++){
        int k = j + 8*r;
        int wrk = (k <= 32) ? k : 64 - k;
        float sgn = (k <= 32) ? 1.f : -1.f;
        int base = (lc_g*33 + wrk)*9;
        float2 y0 = sy[base + 2*pr];
        float2 y1 = sy[base + 2*pr + 1];
        v[r] = make_float2(y0.x - sgn*y1.y, sgn*y0.y + y1.x);
      }
      fft64r<1>(v, tw, j);
      #pragma unroll
      for (int n1=0;n1<8;n1++){
        int w = 8*n1 + j;
        so[((2*pr    )*64 + w)*12 + lc_g] = v[n1].x * sc;
        so[((2*pr + 1)*64 + w)*12 + lc_g] = v[n1].y * sc;
      }
    }
    __syncthreads();
    // stage C: float4 loads + 128-bit coalesced stores (1024 float4 per chunk)
    #pragma unroll
    for (int ii = 0; ii < 4; ii++){
      int i = tid + ii*256;
      int c4 = i & 1, w = (i >> 1) & 63, hl = i >> 7;
      float4 val = *(const float4*)&so[(hl*64 + w)*12 + c4*4];
      *(float4*)&out[obase + (size_t)((hc*8 + hl)*64 + w)*32 + c4*4] = val;
    }
    __syncthreads();
  }
}

extern "C" void kernel_launch(void* const* d_in, const int* in_sizes, int n_in,
                              void* d_out, int out_size){
  const float* x  = (const float*)d_in[0];
  const float* wA = (const float*)d_in[1];
  const float* bA = (const float*)d_in[2];
  const float* wD = (const float*)d_in[3];
  const float* bD = (const float*)d_in[4];
  const float* wM = (const float*)d_in[5];
  const float* bM = (const float*)d_in[6];
  const float* wG = (const float*)d_in[7];
  const float* bG = (const float*)d_in[8];
  const float* dc = (const float*)d_in[9];
  const float* ke = (const float*)d_in[10];
  const float* ki = (const float*)d_in[11];
  float* out = (float*)d_out;

  k_kf   <<<2*C_,        256>>>(ke, ki);
  k_fwd  <<<B_*T_*4*2,   256>>>(x);                            // 512 blocks
  k_gates<<<B_*T_,       32>>>(wA,bA,wD,bD,wM,bM,wG,bG,dc);
  k_mid  <<<B_*C_*WR_/2, 256>>>();                             // 1056 blocks
  k_inv  <<<B_*T_*4*2,   256>>>(out);                          // 512 blocks
}

// round 16
// speedup vs baseline: 2.9513x; 1.0933x over previous
#include <cuda_runtime.h>
#include <cuda_fp16.h>
#include <math.h>

#define B_ 2
#define T_ 32
#define H_ 64
#define W_ 64
#define C_ 32
#define WR_ 33
#define KS_ 15
#define BTC_ (B_*T_*C_)

__device__ __half2 d_R [B_*C_*WR_*T_*H_];  // (B,C,Wr,T,H) row-FFT output (h spatial)
__device__ __half2 d_Yr[B_*C_*WR_*T_*H_];  // (B,C,Wr,T,H) after col-inv FFT
__device__ float2  d_Kf[2*C_*WR_*H_];      // (2,C,Wr,slot) kernel spectra, slot-permuted
__device__ float   d_ctxp[2*BTC_];         // 2-part ctx partial sums
__device__ float   d_gates[B_*C_*4*T_];    // (B,C,[a,d,m,g],T)

__device__ __forceinline__ float2 cmul(float2 a, float2 b){
  return make_float2(a.x*b.x - a.y*b.y, a.x*b.y + a.y*b.x);
}

// ---------------- register FFT8, DIF + output reorder to natural order ----------------
template<int INV>
__device__ __forceinline__ void fft8r(float2 v[8]){
  const float S = 0.70710678118654752f;
  {
    float2 u, w, d;
    u=v[0]; w=v[4]; v[0]=make_float2(u.x+w.x,u.y+w.y); v[4]=make_float2(u.x-w.x,u.y-w.y);
    u=v[1]; w=v[5]; v[1]=make_float2(u.x+w.x,u.y+w.y); d=make_float2(u.x-w.x,u.y-w.y);
    v[5]= INV? make_float2(S*(d.x-d.y), S*(d.x+d.y)) : make_float2(S*(d.x+d.y), S*(d.y-d.x));
    u=v[2]; w=v[6]; v[2]=make_float2(u.x+w.x,u.y+w.y); d=make_float2(u.x-w.x,u.y-w.y);
    v[6]= INV? make_float2(-d.y, d.x) : make_float2(d.y, -d.x);
    u=v[3]; w=v[7]; v[3]=make_float2(u.x+w.x,u.y+w.y); d=make_float2(u.x-w.x,u.y-w.y);
    v[7]= INV? make_float2(-S*(d.x+d.y), S*(d.x-d.y)) : make_float2(S*(d.y-d.x), -S*(d.x+d.y));
  }
  #pragma unroll
  for (int h=0; h<8; h+=4){
    float2 u, w, d;
    u=v[h];   w=v[h+2]; v[h]  =make_float2(u.x+w.x,u.y+w.y); v[h+2]=make_float2(u.x-w.x,u.y-w.y);
    u=v[h+1]; w=v[h+3]; v[h+1]=make_float2(u.x+w.x,u.y+w.y); d=make_float2(u.x-w.x,u.y-w.y);
    v[h+3]= INV? make_float2(-d.y, d.x) : make_float2(d.y, -d.x);
  }
  #pragma unroll
  for (int h=0; h<8; h+=2){
    float2 u=v[h], w=v[h+1];
    v[h]  =make_float2(u.x+w.x,u.y+w.y);
    v[h+1]=make_float2(u.x-w.x,u.y-w.y);
  }
  float2 t1=v[1]; v[1]=v[4]; v[4]=t1;
  float2 t3=v[3]; v[3]=v[6]; v[6]=t3;
}

// Forward: input (lane j=n2, reg n1): x[8*n1+j] -> output (lane k1, reg k2): X[k1+8*k2]
template<int INV>
__device__ __forceinline__ void fft64r(float2 v[8], const float2 tw[8], int lane8){
  fft8r<INV>(v);
  #pragma unroll
  for (int r=1;r<8;r++){
    float2 w = tw[r];
    if (INV) w.y = -w.y;
    v[r] = cmul(v[r], w);
  }
  #pragma unroll
  for (int m=4; m; m>>=1){
    #pragma unroll
    for (int i=0;i<8;i++){
      if (i & m) continue;
      bool up = (lane8 & m) != 0;
      float2 send = up ? v[i] : v[i+m];
      float2 got;
      got.x = __shfl_xor_sync(0xffffffffu, send.x, m);
      got.y = __shfl_xor_sync(0xffffffffu, send.y, m);
      if (up) v[i] = got; else v[i+m] = got;
    }
  }
  fft8r<INV>(v);
}

__device__ __forceinline__ void make_tw(float2 tw[8], int j){
  tw[0] = make_float2(1.f, 0.f);
  #pragma unroll
  for (int r=1;r<8;r++){
    float s, c;
    __sincosf(-0.098174770424681f * (float)(j*r), &s, &c);
    tw[r] = make_float2(c, s);
  }
}

// Hermitian partner fetch: rc[r] = Z[(64 - (j+8r)) mod 64], within 8-lane groups.
__device__ __forceinline__ void herm_partner(const float2 v[8], float2 rc[8], int j){
  int src = (8 - j) & 7;
  #pragma unroll
  for (int r=0;r<8;r++){
    float2 send = v[7-r];
    float2 got;
    got.x = __shfl_sync(0xffffffffu, send.x, src, 8);
    got.y = __shfl_sync(0xffffffffu, send.y, src, 8);
    rc[r] = got;
  }
  if (j == 0){
    rc[0]=v[0]; rc[1]=v[7]; rc[2]=v[6]; rc[3]=v[5];
    rc[4]=v[4]; rc[5]=v[3]; rc[6]=v[2]; rc[7]=v[1];
  }
}

// ---------------- kf body: padded rfft2 of conv kernels (uses caller smem pool) ----------------
__device__ void kf_body(float* sm, int tid, int e, int c,
                        const float* __restrict__ ke, const float* __restrict__ ki){
  float2* sb = (float2*)sm;           // [wr][h spatial], 33*64 float2
  const float* kk = (e ? ki : ke) + c*KS_*KS_;
  int j = tid & 7, g = tid >> 3;
  float2 tw[8]; make_tw(tw, j);

  {
    int h0 = g << 1;
    float2 v[8];
    #pragma unroll
    for (int n1=0;n1<8;n1++){
      int w = 8*n1 + j;
      float v0 = 0.f, v1 = 0.f;
      if (w >= 24 && w < 39){
        if (h0   >= 24 && h0   < 39) v0 = kk[(h0  -24)*KS_ + (w-24)];
        if (h0+1 >= 24 && h0+1 < 39) v1 = kk[(h0+1-24)*KS_ + (w-24)];
      }
      v[n1] = make_float2(v0, v1);
    }
    fft64r<0>(v, tw, j);
    float2 rc[8];
    herm_partner(v, rc, j);
    #pragma unroll
    for (int r=0;r<8;r++){
      int k = j + 8*r;
      if (k <= 32){
        float2 A  = make_float2(0.5f*(v[r].x + rc[r].x), 0.5f*(v[r].y - rc[r].y));
        float2 Bv = make_float2(0.5f*(v[r].y + rc[r].y), 0.5f*(rc[r].x - v[r].x));
        sb[k*64 + h0    ] = A;
        sb[k*64 + h0 + 1] = Bv;
      }
    }
  }
  __syncthreads();
  size_t kb = ((size_t)(e*C_ + c)*WR_)*64;
  {
    int wr = g;
    float2 v[8];
    #pragma unroll
    for (int n1=0;n1<8;n1++) v[n1] = sb[wr*64 + 8*n1 + j];
    fft64r<0>(v, tw, j);
    #pragma unroll
    for (int r=0;r<8;r++) d_Kf[kb + (size_t)wr*64 + r*8 + j] = v[r];
  }
  if (tid < 32){
    float2 v[8];
    #pragma unroll
    for (int n1=0;n1<8;n1++) v[n1] = sb[32*64 + 8*n1 + j];
    fft64r<0>(v, tw, j);
    if ((tid >> 3) == 0){
      #pragma unroll
      for (int r=0;r<8;r++) d_Kf[kb + (size_t)32*64 + r*8 + j] = v[r];
    }
  }
}

// ---------------- K1: row rfft of x (blocks <512) + kernel spectra (blocks >=512) ----------------
__global__ void k_fwd(const float* __restrict__ x,
                      const float* __restrict__ ke, const float* __restrict__ ki){
  __shared__ __align__(16) float sm[11520];   // overlay pool (46KB)
  __shared__ float wsum[8][2][4];
  int tid = threadIdx.x, bid = blockIdx.x;

  if (bid >= 512){
    int eb = bid - 512;
    kf_body(sm, tid, eb >> 5, eb & 31, ke, ki);
    return;
  }

  float*  sx  = sm;                      // [hl8][w64][c8 pad12], 6144 floats
  float2* stg = (float2*)(sm + 6144);    // [c8][wr33][hl8 pad10], 2640 float2

  int hh = bid & 1, cg = (bid>>1) & 3, t = (bid>>3) & 31, b = bid >> 8;
  int c0 = cg*8;
  int j = tid & 7, g = tid >> 3;        // 32 groups of 8 lanes
  int p = g & 3, hl8 = g >> 2;          // channel pair 0..3, local h 0..7
  int c4 = tid & 1;                     // load-phase 4-channel group
  float2 tw[8]; make_tw(tw, j);
  const float* xb = x + (size_t)(b*T_ + t)*H_*W_*C_ + c0;
  float acc[4] = {0.f, 0.f, 0.f, 0.f};
  uint2* dR2 = (uint2*)d_R;

  for (int hc = hh*4; hc < hh*4 + 4; hc++){
    // float4 coalesced loads: i = hl*128 + w*2 + c4
    #pragma unroll
    for (int k4 = 0; k4 < 4; k4++){
      int i = tid + k4*256;
      int w = (i >> 1) & 63, hl = i >> 7;
      float4 zv = *(const float4*)(xb + (size_t)((hc*8 + hl)*64 + w)*C_ + c4*4);
      *(float4*)&sx[(hl*64 + w)*12 + c4*4] = zv;
      acc[0] += zv.x; acc[1] += zv.y; acc[2] += zv.z; acc[3] += zv.w;
    }
    __syncthreads();
    {
      float2 v[8];
      #pragma unroll
      for (int n1=0;n1<8;n1++)
        v[n1] = *(const float2*)&sx[(hl8*64 + 8*n1 + j)*12 + 2*p];
      fft64r<0>(v, tw, j);
      float2 rc[8];
      herm_partner(v, rc, j);
      #pragma unroll
      for (int r=0;r<8;r++){
        int k = j + 8*r;
        if (k <= 32){
          float2 A  = make_float2(0.5f*(v[r].x + rc[r].x), 0.5f*(v[r].y - rc[r].y));
          float2 Bv = make_float2(0.5f*(v[r].y + rc[r].y), 0.5f*(rc[r].x - v[r].x));
          stg[((2*p    )*33 + k)*10 + hl8] = A;
          stg[((2*p + 1)*33 + k)*10 + hl8] = Bv;
        }
      }
    }
    __syncthreads();
    // uint2 stores (2 h per STG.64)
    for (int i = tid; i < 8*33*4; i += 256){
      int hp = i & 3;
      int wr = (i >> 2) % 33;
      int c  = i / 132;
      float2 z0 = stg[(c*33 + wr)*10 + 2*hp];
      float2 z1 = stg[(c*33 + wr)*10 + 2*hp + 1];
      uint2 val;
      *(__half2*)&val.x = __floats2half2_rn(z0.x, z0.y);
      *(__half2*)&val.y = __floats2half2_rn(z1.x, z1.y);
      dR2[((size_t)(b*C_ + c0 + c)*WR_ + wr)*1024 + t*32 + hc*4 + hp] = val;
    }
    __syncthreads();
  }
  // ctx partial reduction: classes by c4 (tid&1)
  #pragma unroll
  for (int m=2; m<=16; m<<=1){
    #pragma unroll
    for (int q=0;q<4;q++) acc[q] += __shfl_xor_sync(0xffffffffu, acc[q], m);
  }
  int lane = tid & 31, warp = tid >> 5;
  if (lane < 2){
    #pragma unroll
    for (int q=0;q<4;q++) wsum[warp][lane][q] = acc[q];
  }
  __syncthreads();
  if (tid < 8){
    float s = 0.f;
    #pragma unroll
    for (int w=0;w<8;w++) s += wsum[w][tid>>2][tid&3];
    d_ctxp[hh*BTC_ + (b*T_ + t)*C_ + c0 + tid] = s * (1.0f/4096.0f);
  }
}

// ---------------- K2: gates (tiny GEMMs, coalesced ctx) ----------------
__global__ void k_gates(const float* __restrict__ wA, const float* __restrict__ bA,
                        const float* __restrict__ wD, const float* __restrict__ bD,
                        const float* __restrict__ wM, const float* __restrict__ bM,
                        const float* __restrict__ wG, const float* __restrict__ bG,
                        const float* __restrict__ decay){
  __shared__ float sctx[32];
  int bt = blockIdx.x;
  int c = threadIdx.x;
  sctx[c] = d_ctxp[bt*32 + c] + d_ctxp[BTC_ + bt*32 + c];
  __syncwarp();
  float za = bA[c], zd = bD[c], zm = bM[c], zg = bG[c];
  #pragma unroll
  for (int k = 0; k < 32; k++){
    float v = sctx[k];
    za += v * wA[k*32 + c];
    zd += v * wD[k*32 + c];
    zm += v * wM[k*32 + c];
    zg += v * wG[k*32 + c];
  }
  float dec = fminf(fmaxf(decay[c], 0.1f), 0.99f);
  float ga = dec / (1.0f + expf(-za));
  float gd = dec / (1.0f + expf(-zd));
  float gm = (zm > 20.0f) ? zm : log1pf(expf(zm));
  float gg = (zg > 20.0f) ? zg : log1pf(expf(zg));
  int b = bt >> 5, t = bt & 31;
  int base = (b*32 + c)*128 + t;
  d_gates[base +  0] = ga;
  d_gates[base + 32] = gd;
  d_gates[base + 64] = gm;
  d_gates[base + 96] = gg;
}

// ---------------- K4: 2 tiles/block, float2 smem (pitch 72): FFT + recurrence + iFFT ----------------
__global__ void k_mid(){
  __shared__ float2 syc[2][32*72];   // [t][slot] pitch 72 float2 (576B row: conflict-free)
  __shared__ float  sg[2][128];
  int tid = threadIdx.x;
  int b0 = blockIdx.x * 2;
  int j = tid & 7, t = tid >> 3;
  float2 tw[8]; make_tw(tw, j);

  if (tid < 128) sg[0][tid]       = d_gates[(b0/33)*128 + tid];
  else           sg[1][tid - 128] = d_gates[((b0+1)/33)*128 + (tid - 128)];

  #pragma unroll
  for (int tt=0; tt<2; tt++){
    size_t rbase = (size_t)(b0 + tt) * 2048;
    float2 v[8];
    #pragma unroll
    for (int n1=0;n1<8;n1++) v[n1] = __half22float2(d_R[rbase + t*64 + 8*n1 + j]);
    fft64r<0>(v, tw, j);
    #pragma unroll
    for (int r=0;r<8;r++) syc[tt][t*72 + r*8 + j] = v[r];
  }
  __syncthreads();

  if (tid < 128){
    int tt = tid >> 6, slot = tid & 63;
    int bid = b0 + tt;
    int bc = bid / 33;
    int wr = bid - bc*33;
    int c  = bc & 31;
    float2 KE = d_Kf[((size_t)(      c)*WR_ + wr)*64 + slot];
    float2 KI = d_Kf[((size_t)(C_ +  c)*WR_ + wr)*64 + slot];
    float2 X = make_float2(0.f,0.f), Y = make_float2(0.f,0.f);
    float2* p2 = syc[tt];
    const float* g = sg[tt];
    #pragma unroll
    for (int t2=0; t2<32; t2++){
      float a  = g[t2], dd = g[32+t2], m = g[64+t2], gg = g[96+t2];
      float2 U = p2[t2*72 + slot];
      float2 KIY = cmul(KI, Y);
      float2 KEX = cmul(KE, X);
      float2 nX = make_float2(a*X.x - m*KIY.x + U.x, a*X.y - m*KIY.y + U.y);
      float2 nY = make_float2(gg*KEX.x + dd*Y.x + 1e-10f, gg*KEX.y + dd*Y.y);
      p2[t2*72 + slot] = nY;
      X = nX; Y = nY;
    }
  }
  __syncthreads();

  #pragma unroll
  for (int tt=0; tt<2; tt++){
    size_t rbase = (size_t)(b0 + tt) * 2048;
    float2 v[8];
    #pragma unroll
    for (int r=0;r<8;r++) v[r] = syc[tt][t*72 + r*8 + j];
    fft64r<1>(v, tw, j);
    #pragma unroll
    for (int n1=0;n1<8;n1++)
      d_Yr[rbase + t*64 + 8*n1 + j] = __floats2half2_rn(v[n1].x, v[n1].y);
  }
}

// ---------------- K5: inverse row rfft; fp16-resident smem stage; block=(hc-half,b,t,cg8) ----------------
__global__ void k_inv(float* __restrict__ out){
  __shared__ uint2 sy2[8*33*5];     // [(lc*33+wr)*5 + hp]  hp=h/2 (half2 pair per uint2), pad 5
  __shared__ float so[8*64*12];     // [h8][w64][c8 pad12]  (16B-aligned c4 groups)
  int tid = threadIdx.x, bid = blockIdx.x;
  int hh = bid & 1;
  int cg = (bid >> 1) & 3;
  int t  = (bid >> 3) & 31;
  int b  = bid >> 8;
  int j = tid & 7, g = tid >> 3;
  int lc_g = g & 7, pr = g >> 3;     // group channel, local h-pair (0..3)
  float2 tw[8]; make_tw(tw, j);
  const float sc = 1.0f/4096.0f;
  size_t obase = ((size_t)(b*T_ + t)*4096)*32 + cg*8;
  const uint4* yb4 = (const uint4*)d_Yr + ((size_t)(b*C_ + cg*8)*WR_)*512 + t*16;

  for (int hc = hh*4; hc < hh*4 + 4; hc++){
    // stage A: uint4 loads, fp16-resident uint2 stores (no conversion)
    for (int i = tid; i < 528; i += 256){
      int q = i >> 1, hp2 = i & 1;
      uint4 zz = yb4[(size_t)q*512 + hc*2 + hp2];
      sy2[q*5 + 2*hp2    ] = make_uint2(zz.x, zz.y);
      sy2[q*5 + 2*hp2 + 1] = make_uint2(zz.z, zz.w);
    }
    __syncthreads();
    // stage B: Hermitian-extend + reg iFFT (single uint2 gather per r, convert in regs)
    {
      float2 v[8];
      #pragma unroll
      for (int r=0;r<8;r++){
        int k = j + 8*r;
        int wrk = (k <= 32) ? k : 64 - k;
        float sgn = (k <= 32) ? 1.f : -1.f;
        uint2 u = sy2[(lc_g*33 + wrk)*5 + pr];
        float2 y0 = __half22float2(*(__half2*)&u.x);
        float2 y1 = __half22float2(*(__half2*)&u.y);
        v[r] = make_float2(y0.x - sgn*y1.y, sgn*y0.y + y1.x);
      }
      fft64r<1>(v, tw, j);
      #pragma unroll
      for (int n1=0;n1<8;n1++){
        int w = 8*n1 + j;
        so[((2*pr    )*64 + w)*12 + lc_g] = v[n1].x * sc;
        so[((2*pr + 1)*64 + w)*12 + lc_g] = v[n1].y * sc;
      }
    }
    __syncthreads();
    // stage C: float4 loads + 128-bit coalesced stores (1024 float4 per chunk)
    #pragma unroll
    for (int ii = 0; ii < 4; ii++){
      int i = tid + ii*256;
      int c4 = i & 1, w = (i >> 1) & 63, hl = i >> 7;
      float4 val = *(const float4*)&so[(hl*64 + w)*12 + c4*4];
      *(float4*)&out[obase + (size_t)((hc*8 + hl)*64 + w)*32 + c4*4] = val;
    }
    __syncthreads();
  }
}

extern "C" void kernel_launch(void* const* d_in, const int* in_sizes, int n_in,
                              void* d_out, int out_size){
  const float* x  = (const float*)d_in[0];
  const float* wA = (const float*)d_in[1];
  const float* bA = (const float*)d_in[2];
  const float* wD = (const float*)d_in[3];
  const float* bD = (const float*)d_in[4];
  const float* wM = (const float*)d_in[5];
  const float* bM = (const float*)d_in[6];
  const float* wG = (const float*)d_in[7];
  const float* bG = (const float*)d_in[8];
  const float* dc = (const float*)d_in[9];
  const float* ke = (const float*)d_in[10];
  const float* ki = (const float*)d_in[11];
  float* out = (float*)d_out;

  k_fwd  <<<512 + 2*C_,  256>>>(x, ke, ki);                    // fwd blocks + kf blocks
  k_gates<<<B_*T_,       32>>>(wA,bA,wD,bD,wM,bM,wG,bG,dc);
  k_mid  <<<B_*C_*WR_/2, 256>>>();                             // 1056 blocks
  k_inv  <<<B_*T_*4*2,   256>>>(out);                          // 512 blocks
}

// round 17
// speedup vs baseline: 3.1243x; 1.0586x over previous
#include <cuda_runtime.h>
#include <cuda_fp16.h>
#include <math.h>

#define B_ 2
#define T_ 32
#define H_ 64
#define W_ 64
#define C_ 32
#define WR_ 33
#define KS_ 15
#define BTC_ (B_*T_*C_)

__device__ __half2 d_R [B_*C_*WR_*T_*H_];  // (B,C,Wr,T,H) row-FFT output (h spatial)
__device__ __half2 d_Yr[B_*C_*WR_*T_*H_];  // (B,C,Wr,T,H) after col-inv FFT
__device__ float2  d_Kf[2*C_*WR_*H_];      // (2,C,Wr,slot) kernel spectra, slot-permuted
__device__ float   d_ctxp[4*BTC_];         // 4-part ctx partial sums
__device__ float   d_gates[B_*C_*4*T_];    // (B,C,[a,d,m,g],T)

__device__ __forceinline__ float2 cmul(float2 a, float2 b){
  return make_float2(a.x*b.x - a.y*b.y, a.x*b.y + a.y*b.x);
}

// ---------------- register FFT8, DIF + output reorder to natural order ----------------
template<int INV>
__device__ __forceinline__ void fft8r(float2 v[8]){
  const float S = 0.70710678118654752f;
  {
    float2 u, w, d;
    u=v[0]; w=v[4]; v[0]=make_float2(u.x+w.x,u.y+w.y); v[4]=make_float2(u.x-w.x,u.y-w.y);
    u=v[1]; w=v[5]; v[1]=make_float2(u.x+w.x,u.y+w.y); d=make_float2(u.x-w.x,u.y-w.y);
    v[5]= INV? make_float2(S*(d.x-d.y), S*(d.x+d.y)) : make_float2(S*(d.x+d.y), S*(d.y-d.x));
    u=v[2]; w=v[6]; v[2]=make_float2(u.x+w.x,u.y+w.y); d=make_float2(u.x-w.x,u.y-w.y);
    v[6]= INV? make_float2(-d.y, d.x) : make_float2(d.y, -d.x);
    u=v[3]; w=v[7]; v[3]=make_float2(u.x+w.x,u.y+w.y); d=make_float2(u.x-w.x,u.y-w.y);
    v[7]= INV? make_float2(-S*(d.x+d.y), S*(d.x-d.y)) : make_float2(S*(d.y-d.x), -S*(d.x+d.y));
  }
  #pragma unroll
  for (int h=0; h<8; h+=4){
    float2 u, w, d;
    u=v[h];   w=v[h+2]; v[h]  =make_float2(u.x+w.x,u.y+w.y); v[h+2]=make_float2(u.x-w.x,u.y-w.y);
    u=v[h+1]; w=v[h+3]; v[h+1]=make_float2(u.x+w.x,u.y+w.y); d=make_float2(u.x-w.x,u.y-w.y);
    v[h+3]= INV? make_float2(-d.y, d.x) : make_float2(d.y, -d.x);
  }
  #pragma unroll
  for (int h=0; h<8; h+=2){
    float2 u=v[h], w=v[h+1];
    v[h]  =make_float2(u.x+w.x,u.y+w.y);
    v[h+1]=make_float2(u.x-w.x,u.y-w.y);
  }
  float2 t1=v[1]; v[1]=v[4]; v[4]=t1;
  float2 t3=v[3]; v[3]=v[6]; v[6]=t3;
}

// Forward: input (lane j=n2, reg n1): x[8*n1+j] -> output (lane k1, reg k2): X[k1+8*k2]
template<int INV>
__device__ __forceinline__ void fft64r(float2 v[8], const float2 tw[8], int lane8){
  fft8r<INV>(v);
  #pragma unroll
  for (int r=1;r<8;r++){
    float2 w = tw[r];
    if (INV) w.y = -w.y;
    v[r] = cmul(v[r], w);
  }
  #pragma unroll
  for (int m=4; m; m>>=1){
    #pragma unroll
    for (int i=0;i<8;i++){
      if (i & m) continue;
      bool up = (lane8 & m) != 0;
      float2 send = up ? v[i] : v[i+m];
      float2 got;
      got.x = __shfl_xor_sync(0xffffffffu, send.x, m);
      got.y = __shfl_xor_sync(0xffffffffu, send.y, m);
      if (up) v[i] = got; else v[i+m] = got;
    }
  }
  fft8r<INV>(v);
}

__device__ __forceinline__ void make_tw(float2 tw[8], int j){
  tw[0] = make_float2(1.f, 0.f);
  #pragma unroll
  for (int r=1;r<8;r++){
    float s, c;
    __sincosf(-0.098174770424681f * (float)(j*r), &s, &c);
    tw[r] = make_float2(c, s);
  }
}

// Hermitian partner fetch: rc[r] = Z[(64 - (j+8r)) mod 64], within 8-lane groups.
__device__ __forceinline__ void herm_partner(const float2 v[8], float2 rc[8], int j){
  int src = (8 - j) & 7;
  #pragma unroll
  for (int r=0;r<8;r++){
    float2 send = v[7-r];
    float2 got;
    got.x = __shfl_sync(0xffffffffu, send.x, src, 8);
    got.y = __shfl_sync(0xffffffffu, send.y, src, 8);
    rc[r] = got;
  }
  if (j == 0){
    rc[0]=v[0]; rc[1]=v[7]; rc[2]=v[6]; rc[3]=v[5];
    rc[4]=v[4]; rc[5]=v[3]; rc[6]=v[2]; rc[7]=v[1];
  }
}

// ---------------- kf body: padded rfft2 of conv kernels (uses caller smem pool) ----------------
__device__ void kf_body(float* sm, int tid, int e, int c,
                        const float* __restrict__ ke, const float* __restrict__ ki){
  float2* sb = (float2*)sm;           // [wr][h spatial], 33*64 float2
  const float* kk = (e ? ki : ke) + c*KS_*KS_;
  int j = tid & 7, g = tid >> 3;
  float2 tw[8]; make_tw(tw, j);

  {
    int h0 = g << 1;
    float2 v[8];
    #pragma unroll
    for (int n1=0;n1<8;n1++){
      int w = 8*n1 + j;
      float v0 = 0.f, v1 = 0.f;
      if (w >= 24 && w < 39){
        if (h0   >= 24 && h0   < 39) v0 = kk[(h0  -24)*KS_ + (w-24)];
        if (h0+1 >= 24 && h0+1 < 39) v1 = kk[(h0+1-24)*KS_ + (w-24)];
      }
      v[n1] = make_float2(v0, v1);
    }
    fft64r<0>(v, tw, j);
    float2 rc[8];
    herm_partner(v, rc, j);
    #pragma unroll
    for (int r=0;r<8;r++){
      int k = j + 8*r;
      if (k <= 32){
        float2 A  = make_float2(0.5f*(v[r].x + rc[r].x), 0.5f*(v[r].y - rc[r].y));
        float2 Bv = make_float2(0.5f*(v[r].y + rc[r].y), 0.5f*(rc[r].x - v[r].x));
        sb[k*64 + h0    ] = A;
        sb[k*64 + h0 + 1] = Bv;
      }
    }
  }
  __syncthreads();
  size_t kb = ((size_t)(e*C_ + c)*WR_)*64;
  {
    int wr = g;
    float2 v[8];
    #pragma unroll
    for (int n1=0;n1<8;n1++) v[n1] = sb[wr*64 + 8*n1 + j];
    fft64r<0>(v, tw, j);
    #pragma unroll
    for (int r=0;r<8;r++) d_Kf[kb + (size_t)wr*64 + r*8 + j] = v[r];
  }
  if (tid < 32){
    float2 v[8];
    #pragma unroll
    for (int n1=0;n1<8;n1++) v[n1] = sb[32*64 + 8*n1 + j];
    fft64r<0>(v, tw, j);
    if ((tid >> 3) == 0){
      #pragma unroll
      for (int r=0;r<8;r++) d_Kf[kb + (size_t)32*64 + r*8 + j] = v[r];
    }
  }
}

// ---------------- K1: row rfft of x (blocks <1024) + kernel spectra (blocks >=1024) ----------------
__global__ void k_fwd(const float* __restrict__ x,
                      const float* __restrict__ ke, const float* __restrict__ ki){
  __shared__ __align__(16) float sm[11520];   // overlay pool (46KB)
  __shared__ float wsum[8][2][4];
  int tid = threadIdx.x, bid = blockIdx.x;

  if (bid >= 1024){
    int eb = bid - 1024;
    kf_body(sm, tid, eb >> 5, eb & 31, ke, ki);
    return;
  }

  float*  sx  = sm;                      // [hl8][w64][c8 pad12], 6144 floats
  float2* stg = (float2*)(sm + 6144);    // [c8][wr33][hl8 pad10], 2640 float2

  int hh = bid & 3, cg = (bid>>2) & 3, t = (bid>>4) & 31, b = bid >> 9;
  int c0 = cg*8;
  int j = tid & 7, g = tid >> 3;        // 32 groups of 8 lanes
  int p = g & 3, hl8 = g >> 2;          // channel pair 0..3, local h 0..7
  int c4 = tid & 1;                     // load-phase 4-channel group
  float2 tw[8]; make_tw(tw, j);
  const float* xb = x + (size_t)(b*T_ + t)*H_*W_*C_ + c0;
  float acc[4] = {0.f, 0.f, 0.f, 0.f};
  uint2* dR2 = (uint2*)d_R;

  for (int hc = hh*2; hc < hh*2 + 2; hc++){
    // float4 coalesced loads: i = hl*128 + w*2 + c4
    #pragma unroll
    for (int k4 = 0; k4 < 4; k4++){
      int i = tid + k4*256;
      int w = (i >> 1) & 63, hl = i >> 7;
      float4 zv = *(const float4*)(xb + (size_t)((hc*8 + hl)*64 + w)*C_ + c4*4);
      *(float4*)&sx[(hl*64 + w)*12 + c4*4] = zv;
      acc[0] += zv.x; acc[1] += zv.y; acc[2] += zv.z; acc[3] += zv.w;
    }
    __syncthreads();
    {
      float2 v[8];
      #pragma unroll
      for (int n1=0;n1<8;n1++)
        v[n1] = *(const float2*)&sx[(hl8*64 + 8*n1 + j)*12 + 2*p];
      fft64r<0>(v, tw, j);
      float2 rc[8];
      herm_partner(v, rc, j);
      #pragma unroll
      for (int r=0;r<8;r++){
        int k = j + 8*r;
        if (k <= 32){
          float2 A  = make_float2(0.5f*(v[r].x + rc[r].x), 0.5f*(v[r].y - rc[r].y));
          float2 Bv = make_float2(0.5f*(v[r].y + rc[r].y), 0.5f*(rc[r].x - v[r].x));
          stg[((2*p    )*33 + k)*10 + hl8] = A;
          stg[((2*p + 1)*33 + k)*10 + hl8] = Bv;
        }
      }
    }
    __syncthreads();
    // uint2 stores (2 h per STG.64)
    for (int i = tid; i < 8*33*4; i += 256){
      int hp = i & 3;
      int wr = (i >> 2) % 33;
      int c  = i / 132;
      float2 z0 = stg[(c*33 + wr)*10 + 2*hp];
      float2 z1 = stg[(c*33 + wr)*10 + 2*hp + 1];
      uint2 val;
      *(__half2*)&val.x = __floats2half2_rn(z0.x, z0.y);
      *(__half2*)&val.y = __floats2half2_rn(z1.x, z1.y);
      dR2[((size_t)(b*C_ + c0 + c)*WR_ + wr)*1024 + t*32 + hc*4 + hp] = val;
    }
    __syncthreads();
  }
  // ctx partial reduction: classes by c4 (tid&1)
  #pragma unroll
  for (int m=2; m<=16; m<<=1){
    #pragma unroll
    for (int q=0;q<4;q++) acc[q] += __shfl_xor_sync(0xffffffffu, acc[q], m);
  }
  int lane = tid & 31, warp = tid >> 5;
  if (lane < 2){
    #pragma unroll
    for (int q=0;q<4;q++) wsum[warp][lane][q] = acc[q];
  }
  __syncthreads();
  if (tid < 8){
    float s = 0.f;
    #pragma unroll
    for (int w=0;w<8;w++) s += wsum[w][tid>>2][tid&3];
    d_ctxp[hh*BTC_ + (b*T_ + t)*C_ + c0 + tid] = s * (1.0f/4096.0f);
  }
}

// ---------------- K2: gates (tiny GEMMs, coalesced ctx) ----------------
__global__ void k_gates(const float* __restrict__ wA, const float* __restrict__ bA,
                        const float* __restrict__ wD, const float* __restrict__ bD,
                        const float* __restrict__ wM, const float* __restrict__ bM,
                        const float* __restrict__ wG, const float* __restrict__ bG,
                        const float* __restrict__ decay){
  __shared__ float sctx[32];
  int bt = blockIdx.x;
  int c = threadIdx.x;
  sctx[c] = d_ctxp[bt*32 + c] + d_ctxp[BTC_ + bt*32 + c]
          + d_ctxp[2*BTC_ + bt*32 + c] + d_ctxp[3*BTC_ + bt*32 + c];
  __syncwarp();
  float za = bA[c], zd = bD[c], zm = bM[c], zg = bG[c];
  #pragma unroll
  for (int k = 0; k < 32; k++){
    float v = sctx[k];
    za += v * wA[k*32 + c];
    zd += v * wD[k*32 + c];
    zm += v * wM[k*32 + c];
    zg += v * wG[k*32 + c];
  }
  float dec = fminf(fmaxf(decay[c], 0.1f), 0.99f);
  float ga = dec / (1.0f + expf(-za));
  float gd = dec / (1.0f + expf(-zd));
  float gm = (zm > 20.0f) ? zm : log1pf(expf(zm));
  float gg = (zg > 20.0f) ? zg : log1pf(expf(zg));
  int b = bt >> 5, t = bt & 31;
  int base = (b*32 + c)*128 + t;
  d_gates[base +  0] = ga;
  d_gates[base + 32] = gd;
  d_gates[base + 64] = gm;
  d_gates[base + 96] = gg;
}

// ---------------- K4: 2 tiles/block, float2 smem (pitch 72): FFT + recurrence + iFFT ----------------
__global__ void k_mid(){
  __shared__ float2 syc[2][32*72];   // [t][slot] pitch 72 float2 (576B row: conflict-free)
  __shared__ float  sg[2][128];
  int tid = threadIdx.x;
  int b0 = blockIdx.x * 2;
  int j = tid & 7, t = tid >> 3;
  float2 tw[8]; make_tw(tw, j);

  if (tid < 128) sg[0][tid]       = d_gates[(b0/33)*128 + tid];
  else           sg[1][tid - 128] = d_gates[((b0+1)/33)*128 + (tid - 128)];

  #pragma unroll
  for (int tt=0; tt<2; tt++){
    size_t rbase = (size_t)(b0 + tt) * 2048;
    float2 v[8];
    #pragma unroll
    for (int n1=0;n1<8;n1++) v[n1] = __half22float2(d_R[rbase + t*64 + 8*n1 + j]);
    fft64r<0>(v, tw, j);
    #pragma unroll
    for (int r=0;r<8;r++) syc[tt][t*72 + r*8 + j] = v[r];
  }
  __syncthreads();

  if (tid < 128){
    int tt = tid >> 6, slot = tid & 63;
    int bid = b0 + tt;
    int bc = bid / 33;
    int wr = bid - bc*33;
    int c  = bc & 31;
    float2 KE = d_Kf[((size_t)(      c)*WR_ + wr)*64 + slot];
    float2 KI = d_Kf[((size_t)(C_ +  c)*WR_ + wr)*64 + slot];
    float2 X = make_float2(0.f,0.f), Y = make_float2(0.f,0.f);
    float2* p2 = syc[tt];
    const float* g = sg[tt];
    #pragma unroll
    for (int t2=0; t2<32; t2++){
      float a  = g[t2], dd = g[32+t2], m = g[64+t2], gg = g[96+t2];
      float2 U = p2[t2*72 + slot];
      float2 KIY = cmul(KI, Y);
      float2 KEX = cmul(KE, X);
      float2 nX = make_float2(a*X.x - m*KIY.x + U.x, a*X.y - m*KIY.y + U.y);
      float2 nY = make_float2(gg*KEX.x + dd*Y.x + 1e-10f, gg*KEX.y + dd*Y.y);
      p2[t2*72 + slot] = nY;
      X = nX; Y = nY;
    }
  }
  __syncthreads();

  #pragma unroll
  for (int tt=0; tt<2; tt++){
    size_t rbase = (size_t)(b0 + tt) * 2048;
    float2 v[8];
    #pragma unroll
    for (int r=0;r<8;r++) v[r] = syc[tt][t*72 + r*8 + j];
    fft64r<1>(v, tw, j);
    #pragma unroll
    for (int n1=0;n1<8;n1++)
      d_Yr[rbase + t*64 + 8*n1 + j] = __floats2half2_rn(v[n1].x, v[n1].y);
  }
}

// ---------------- K5: inverse row rfft; ONE h-chunk per block; block=(hc,b,t,cg8) ----------------
__global__ void k_inv(float* __restrict__ out){
  __shared__ uint2 sy2[8*33*5];     // [(lc*33+wr)*5 + hp]  hp=h/2 (half2 pair per uint2), pad 5
  __shared__ float so[8*64*12];     // [h8][w64][c8 pad12]  (16B-aligned c4 groups)
  int tid = threadIdx.x, bid = blockIdx.x;
  int hc = bid & 7;
  int cg = (bid >> 3) & 3;
  int t  = (bid >> 5) & 31;
  int b  = bid >> 10;
  int j = tid & 7, g = tid >> 3;
  int lc_g = g & 7, pr = g >> 3;     // group channel, local h-pair (0..3)
  float2 tw[8]; make_tw(tw, j);
  const float sc = 1.0f/4096.0f;
  size_t obase = ((size_t)(b*T_ + t)*4096)*32 + cg*8;
  const uint4* yb4 = (const uint4*)d_Yr + ((size_t)(b*C_ + cg*8)*WR_)*512 + t*16;

  // stage A: uint4 loads, fp16-resident uint2 stores (no conversion)
  for (int i = tid; i < 528; i += 256){
    int q = i >> 1, hp2 = i & 1;
    uint4 zz = yb4[(size_t)q*512 + hc*2 + hp2];
    sy2[q*5 + 2*hp2    ] = make_uint2(zz.x, zz.y);
    sy2[q*5 + 2*hp2 + 1] = make_uint2(zz.z, zz.w);
  }
  __syncthreads();
  // stage B: Hermitian-extend + reg iFFT (single uint2 gather per r, convert in regs)
  {
    float2 v[8];
    #pragma unroll
    for (int r=0;r<8;r++){
      int k = j + 8*r;
      int wrk = (k <= 32) ? k : 64 - k;
      float sgn = (k <= 32) ? 1.f : -1.f;
      uint2 u = sy2[(lc_g*33 + wrk)*5 + pr];
      float2 y0 = __half22float2(*(__half2*)&u.x);
      float2 y1 = __half22float2(*(__half2*)&u.y);
      v[r] = make_float2(y0.x - sgn*y1.y, sgn*y0.y + y1.x);
    }
    fft64r<1>(v, tw, j);
    #pragma unroll
    for (int n1=0;n1<8;n1++){
      int w = 8*n1 + j;
      so[((2*pr    )*64 + w)*12 + lc_g] = v[n1].x * sc;
      so[((2*pr + 1)*64 + w)*12 + lc_g] = v[n1].y * sc;
    }
  }
  __syncthreads();
  // stage C: float4 loads + 128-bit coalesced stores (1024 float4)
  #pragma unroll
  for (int ii = 0; ii < 4; ii++){
    int i = tid + ii*256;
    int c4 = i & 1, w = (i >> 1) & 63, hl = i >> 7;
    float4 val = *(const float4*)&so[(hl*64 + w)*12 + c4*4];
    *(float4*)&out[obase + (size_t)((hc*8 + hl)*64 + w)*32 + c4*4] = val;
  }
}

extern "C" void kernel_launch(void* const* d_in, const int* in_sizes, int n_in,
                              void* d_out, int out_size){
  const float* x  = (const float*)d_in[0];
  const float* wA = (const float*)d_in[1];
  const float* bA = (const float*)d_in[2];
  const float* wD = (const float*)d_in[3];
  const float* bD = (const float*)d_in[4];
  const float* wM = (const float*)d_in[5];
  const float* bM = (const float*)d_in[6];
  const float* wG = (const float*)d_in[7];
  const float* bG = (const float*)d_in[8];
  const float* dc = (const float*)d_in[9];
  const float* ke = (const float*)d_in[10];
  const float* ki = (const float*)d_in[11];
  float* out = (float*)d_out;

  k_fwd  <<<1024 + 2*C_, 256>>>(x, ke, ki);                    // fwd blocks + kf blocks
  k_gates<<<B_*T_,       32>>>(wA,bA,wD,bD,wM,bM,wG,bG,dc);
  k_mid  <<<B_*C_*WR_/2, 256>>>();                             // 1056 blocks
  k_inv  <<<B_*T_*4*8,   256>>>(out);                          // 2048 blocks, 1 chunk each
}